// round 5
// baseline (speedup 1.0000x reference)
#include <cuda_runtime.h>
#include <cuda_bf16.h>
#include <math.h>

#define BG   128
#define NPG  256
#define EPG  2048
#define EMB  256
#define NL   5
#define NTOT (BG*NPG)     // 32768 nodes
#define ETOT (BG*EPG)     // 262144 edges

typedef unsigned long long ull;

// ------------------------------ scratch (device globals; no allocs) ---------
__device__ ull   g_pack[(size_t)BG*NPG*NPG];
__device__ float g_A   [(size_t)BG*NPG*NPG];
__device__ float g_h  [NTOT*EMB];
__device__ float g_x1 [NTOT*EMB];
__device__ float g_x2 [NTOT*EMB];
__device__ float g_hin[NTOT*EMB];
__device__ float g_z  [NTOT*EMB];
__device__ float g_t  [NTOT*2*EMB];
__device__ float g_h2 [NTOT*EMB];
__device__ float g_vn [BG*EMB];
__device__ float g_vt [BG*EMB];
__device__ float g_vh [BG*2*EMB];
__device__ float g_ewt[16];
__device__ int   g_deg[NTOT];
__device__ int   g_ptr[NTOT];
__device__ int   g_cur[NTOT];
__device__ int   g_csrc[ETOT];
__device__ int   g_cea [ETOT];
__device__ float g_sum[2*EMB];
__device__ float g_sq [2*EMB];
__device__ float g_sc1[2*EMB];
__device__ float g_sh1[2*EMB];
__device__ float g_sc2[EMB];
__device__ float g_sh2[EMB];

// ------------------------------ setup kernels -------------------------------
__global__ void k_zero() {
    size_t i = (size_t)blockIdx.x * 256 + threadIdx.x;
    if (i < (size_t)BG*NPG*NPG) g_pack[i] = 0ull;
    if (i < NTOT) g_deg[i] = 0;
}

__global__ void k_ewt(const float* __restrict__ bh, const float* __restrict__ w,
                      const float* __restrict__ b) {
    int warp = threadIdx.x >> 5, lane = threadIdx.x & 31;
    if (warp < 16) {
        float v = bh[warp*64 + lane] * w[lane] + bh[warp*64 + 32 + lane] * w[32 + lane];
        #pragma unroll
        for (int o = 16; o; o >>= 1) v += __shfl_down_sync(0xffffffffu, v, o);
        if (lane == 0) g_ewt[warp] = 1.f / (1.f + expf(-(v + b[0])));
    }
}

__global__ void k_scatter(const int* __restrict__ lei, const int* __restrict__ eai) {
    int idx = blockIdx.x * 256 + threadIdx.x;
    if (idx >= ETOT) return;
    int b = idx / EPG, k = idx - b * EPG;
    int s = lei[(size_t)b*2*EPG + k];
    int d = lei[(size_t)b*2*EPG + EPG + k];
    int t = eai[idx];
    float w = g_ewt[t];
    ull key = ((ull)(k + 1) << 32) | (ull)__float_as_uint(w);
    atomicMax(&g_pack[(size_t)b*NPG*NPG + (size_t)s*NPG + d], key);
    atomicAdd(&g_deg[b*NPG + d], 1);
}

__global__ void k_adjfin() {
    int g = blockIdx.x, tid = threadIdx.x;
    __shared__ float cs[NPG], rs[NPG];
    const ull* P = g_pack + (size_t)g*NPG*NPG;
    float*     A = g_A    + (size_t)g*NPG*NPG;
    float c = 0.f;
    for (int i = 0; i < NPG; i++) {
        ull p = P[(size_t)i*NPG + tid];
        float v = p ? __uint_as_float((unsigned)(p & 0xffffffffu)) : 0.f;
        if (i == tid) v += 1.f;
        A[(size_t)i*NPG + tid] = v;
        c += v;
    }
    cs[tid] = rsqrtf(c);
    __syncthreads();
    float r = 0.f;
    for (int j = 0; j < NPG; j++) r += A[(size_t)tid*NPG + j];
    rs[tid] = rsqrtf(r);
    __syncthreads();
    for (int i = 0; i < NPG; i++)
        A[(size_t)i*NPG + tid] *= cs[i] * rs[tid];
}

__global__ void k_scan() {
    int g = blockIdx.x, tid = threadIdx.x;
    __shared__ int s[NPG];
    int d = g_deg[g*NPG + tid];
    s[tid] = d;
    __syncthreads();
    for (int off = 1; off < NPG; off <<= 1) {
        int v = (tid >= off) ? s[tid - off] : 0;
        __syncthreads();
        s[tid] += v;
        __syncthreads();
    }
    int excl = s[tid] - d;
    g_ptr[g*NPG + tid] = g*EPG + excl;
    g_cur[g*NPG + tid] = g*EPG + excl;
}

__global__ void k_csrfill(const int* __restrict__ lei, const int* __restrict__ eai) {
    int idx = blockIdx.x * 256 + threadIdx.x;
    if (idx >= ETOT) return;
    int b = idx / EPG, k = idx - b * EPG;
    int s = lei[(size_t)b*2*EPG + k];
    int d = lei[(size_t)b*2*EPG + EPG + k];
    int pos = atomicAdd(&g_cur[b*NPG + d], 1);
    g_csrc[pos] = b*NPG + s;
    g_cea [pos] = eai[idx];
}

// h0 = atom_emb[atom_idx]; g_h pre-scaled by 0.25 (the /(order+1))
__global__ void k_gather(const int* __restrict__ aidx, const float* __restrict__ aemb) {
    int idx = blockIdx.x * 256 + threadIdx.x;
    int n = idx >> 8, c = idx & 255;
    float v = aemb[aidx[n]*EMB + c];
    g_h[idx]  = 0.25f * v;
    g_x1[idx] = v;
}

// ------------------------------ bf16x3 tensor-core GEMM (single-stage) ------
// fp32-accurate: x = hi + lo (bf16), A@B ~= Ah@Bh + Ah@Bl + Al@Bh
// CTA tile 128x64x16, 8 warps (4x2), warp tile 32x32, mma.m16n8k16.bf16
#define BM 128
#define BN 64
#define BK 16
#define AST 12     // word stride, conflict-free a-frag LDS
#define BST 72     // word stride (72%32==8), conflict-free b-frag LDS

__device__ __forceinline__ unsigned pack2(float e, float o) {
    unsigned r;
    asm("cvt.rn.bf16x2.f32 %0, %1, %2;" : "=r"(r) : "f"(o), "f"(e));
    return r;
}
__device__ __forceinline__ void split2(float e, float o, unsigned &hi, unsigned &lo) {
    float he = __bfloat162float(__float2bfloat16(e));
    float ho = __bfloat162float(__float2bfloat16(o));
    hi = pack2(e, o);
    lo = pack2(e - he, o - ho);
}

#define MMA_BF16(c, a, b)                                                     \
    asm volatile(                                                             \
        "mma.sync.aligned.m16n8k16.row.col.f32.bf16.bf16.f32 "                \
        "{%0,%1,%2,%3}, {%4,%5,%6,%7}, {%8,%9}, {%0,%1,%2,%3};\n"             \
        : "+f"((c)[0]), "+f"((c)[1]), "+f"((c)[2]), "+f"((c)[3])              \
        : "r"((a)[0]), "r"((a)[1]), "r"((a)[2]), "r"((a)[3]),                 \
          "r"((b)[0]), "r"((b)[1]))

// mode: 0 = C=acc+bias, 1 = C=relu(acc+bias), 2 = C=acc, Y += 0.25*acc
// asc/ash: optional per-K-column transform of A: a = relu(a*asc[k]+ash[k])
// ssum/ssq: optional per-column stats of C (post-bias), atomically accumulated
__global__ void __launch_bounds__(256)
k_mma(const float* __restrict__ A, const float* __restrict__ B,
      const float* __restrict__ bias, float* __restrict__ C, float* __restrict__ Y,
      int M, int N, int K, int mode,
      long strideA, long strideB, long strideC,
      const float* __restrict__ asc, const float* __restrict__ ash,
      float* __restrict__ ssum, float* __restrict__ ssq) {
    A += (size_t)blockIdx.z * strideA;
    B += (size_t)blockIdx.z * strideB;
    C += (size_t)blockIdx.z * strideC;
    if (Y) Y += (size_t)blockIdx.z * strideC;

    __shared__ unsigned Ah[BM][AST], Al[BM][AST];   // [m][k2] packed bf16x2
    __shared__ unsigned Bh[8][BST],  Bl[8][BST];    // [k2][n] packed bf16x2
    __shared__ float s1[BN], s2[BN];

    int tid  = threadIdx.x;
    int lane = tid & 31, warp = tid >> 5;
    int wm = warp >> 1, wn = warp & 1;          // 4x2 warp grid
    int bm = blockIdx.y * BM, bn = blockIdx.x * BN;

    int a_r0 = tid >> 2;
    int a_c  = (tid & 3) << 2;       // k offset (4 floats)
    int a_k2 = (tid & 3) << 1;       // packed word offset
    int b_k2 = tid >> 5;             // 0..7
    int b_n  = lane << 1;            // 0..62

    int gid = lane >> 2, tig = lane & 3;

    bool do_stats = (ssum != nullptr);
    if (do_stats && tid < BN) { s1[tid] = 0.f; s2[tid] = 0.f; }

    float acc[2][4][4];
    #pragma unroll
    for (int i = 0; i < 2; i++)
        #pragma unroll
        for (int j = 0; j < 4; j++)
            #pragma unroll
            for (int r = 0; r < 4; r++) acc[i][j][r] = 0.f;

    for (int k0 = 0; k0 < K; k0 += BK) {
        // ---- load + (optional bn1-relu) + split A tile 128x16 ----
        float4 sc4, sh4;
        if (asc) {
            sc4 = *reinterpret_cast<const float4*>(asc + k0 + a_c);
            sh4 = *reinterpret_cast<const float4*>(ash + k0 + a_c);
        }
        #pragma unroll
        for (int h = 0; h < 2; h++) {
            int r = a_r0 + h*64;
            float4 v = *reinterpret_cast<const float4*>(A + (size_t)(bm + r)*K + k0 + a_c);
            if (asc) {
                v.x = fmaxf(v.x*sc4.x + sh4.x, 0.f);
                v.y = fmaxf(v.y*sc4.y + sh4.y, 0.f);
                v.z = fmaxf(v.z*sc4.z + sh4.z, 0.f);
                v.w = fmaxf(v.w*sc4.w + sh4.w, 0.f);
            }
            unsigned hi0, lo0, hi1, lo1;
            split2(v.x, v.y, hi0, lo0);
            split2(v.z, v.w, hi1, lo1);
            Ah[r][a_k2]   = hi0;  Al[r][a_k2]   = lo0;
            Ah[r][a_k2+1] = hi1;  Al[r][a_k2+1] = lo1;
        }
        // ---- load + split B tile 16x64 ----
        {
            const float* Bp = B + (size_t)(k0 + 2*b_k2)*N + bn + b_n;
            float2 ve = *reinterpret_cast<const float2*>(Bp);
            float2 vo = *reinterpret_cast<const float2*>(Bp + N);
            unsigned hi0, lo0, hi1, lo1;
            split2(ve.x, vo.x, hi0, lo0);
            split2(ve.y, vo.y, hi1, lo1);
            Bh[b_k2][b_n]   = hi0;  Bl[b_k2][b_n]   = lo0;
            Bh[b_k2][b_n+1] = hi1;  Bl[b_k2][b_n+1] = lo1;
        }
        __syncthreads();

        // ---- fragments ----
        unsigned ah[2][4], al[2][4], bh[4][2], bl[4][2];
        #pragma unroll
        for (int mf = 0; mf < 2; mf++) {
            int rm = wm*32 + mf*16 + gid;
            ah[mf][0] = Ah[rm    ][tig    ];
            ah[mf][1] = Ah[rm + 8][tig    ];
            ah[mf][2] = Ah[rm    ][tig + 4];
            ah[mf][3] = Ah[rm + 8][tig + 4];
            al[mf][0] = Al[rm    ][tig    ];
            al[mf][1] = Al[rm + 8][tig    ];
            al[mf][2] = Al[rm    ][tig + 4];
            al[mf][3] = Al[rm + 8][tig + 4];
        }
        #pragma unroll
        for (int nf = 0; nf < 4; nf++) {
            int cn = wn*32 + nf*8 + gid;
            bh[nf][0] = Bh[tig    ][cn];
            bh[nf][1] = Bh[tig + 4][cn];
            bl[nf][0] = Bl[tig    ][cn];
            bl[nf][1] = Bl[tig + 4][cn];
        }

        // ---- 3-product split MMA ----
        #pragma unroll
        for (int mf = 0; mf < 2; mf++)
            #pragma unroll
            for (int nf = 0; nf < 4; nf++) {
                float* c = acc[mf][nf];
                MMA_BF16(c, ah[mf], bl[nf]);
                MMA_BF16(c, al[mf], bh[nf]);
                MMA_BF16(c, ah[mf], bh[nf]);
            }
        __syncthreads();
    }

    // ---- epilogue ----
    float lsum[4][2] = {}, lsq[4][2] = {};
    #pragma unroll
    for (int mf = 0; mf < 2; mf++) {
        #pragma unroll
        for (int nf = 0; nf < 4; nf++) {
            int r0 = bm + wm*32 + mf*16 + gid;
            int c0 = bn + wn*32 + nf*8 + 2*tig;
            float* c = acc[mf][nf];
            #pragma unroll
            for (int half = 0; half < 2; half++) {
                int r = r0 + half*8;
                float v0 = c[half*2+0], v1 = c[half*2+1];
                if (mode != 2) {
                    v0 += bias[c0]; v1 += bias[c0+1];
                    if (do_stats) {
                        lsum[nf][0] += v0;    lsum[nf][1] += v1;
                        lsq [nf][0] += v0*v0; lsq [nf][1] += v1*v1;
                    }
                    if (mode == 1) { v0 = fmaxf(v0, 0.f); v1 = fmaxf(v1, 0.f); }
                    *reinterpret_cast<float2*>(C + (size_t)r*N + c0) = make_float2(v0, v1);
                } else {
                    *reinterpret_cast<float2*>(C + (size_t)r*N + c0) = make_float2(v0, v1);
                    float2* y = reinterpret_cast<float2*>(Y + (size_t)r*N + c0);
                    float2 yo = *y;
                    yo.x += 0.25f*v0; yo.y += 0.25f*v1;
                    *y = yo;
                }
            }
        }
    }
    if (do_stats) {
        #pragma unroll
        for (int nf = 0; nf < 4; nf++) {
            int cl = wn*32 + nf*8 + 2*tig;
            atomicAdd(&s1[cl],   lsum[nf][0]);
            atomicAdd(&s1[cl+1], lsum[nf][1]);
            atomicAdd(&s2[cl],   lsq[nf][0]);
            atomicAdd(&s2[cl+1], lsq[nf][1]);
        }
        __syncthreads();
        if (tid < BN) {
            atomicAdd(&ssum[bn + tid], s1[tid]);
            atomicAdd(&ssq [bn + tid], s2[tid]);
        }
    }
}

// ------------------------------ fused GIN kernels ---------------------------
// hv = T(src) + vn (T = optional bn2+relu of prev layer), writes g_hin,
// aggregates relu(hv_src + eemb) over incoming edges into g_z.
__global__ void k_agg(const float* __restrict__ src,
                      const float* __restrict__ sc, const float* __restrict__ sh,
                      const float* __restrict__ eembL, const float* __restrict__ epsp,
                      const float* __restrict__ vnp, int vnstride) {
    int n = blockIdx.x, c = threadIdx.x;
    int b = n >> 8;
    float vnv = vnp[b*vnstride + c];
    float scv = 1.f, shv = 0.f;
    if (sc) { scv = sc[c]; shv = sh[c]; }
    int start = g_ptr[n], deg = g_deg[n];
    float own = src[(size_t)n*EMB + c];
    if (sc) own = fmaxf(own*scv + shv, 0.f);
    float hvn = own + vnv;
    g_hin[(size_t)n*EMB + c] = hvn;
    float val = 0.f;
    for (int k = 0; k < deg; k++) {
        int s = g_csrc[start + k];
        int t = g_cea [start + k];
        float x = src[(size_t)s*EMB + c];
        if (sc) x = fmaxf(x*scv + shv, 0.f);
        float m = x + vnv + eembL[t*EMB + c];
        val += fmaxf(m, 0.f);
    }
    g_z[(size_t)n*EMB + c] = (1.f + *epsp)*hvn + val;
}

// ------------------------------ batchnorm helpers ---------------------------
__global__ void k_zstat() {
    int i = blockIdx.x * 256 + threadIdx.x;
    if (i < 2*EMB) { g_sum[i] = 0.f; g_sq[i] = 0.f; }
}

__global__ void k_bnfin(const float* __restrict__ g, const float* __restrict__ b,
                        float* __restrict__ osc, float* __restrict__ osh, int C) {
    int c = blockIdx.x * 256 + threadIdx.x;
    if (c >= C) return;
    float mu  = g_sum[c] * (1.f / NTOT);
    float var = g_sq[c] * (1.f / NTOT) - mu * mu;
    float s   = g[c] * rsqrtf(var + 1e-5f);
    osc[c] = s;
    osh[c] = b[c] - mu * s;
}

// final-layer BN apply (no relu) straight to output
__global__ void k_bnout(const float* __restrict__ X, float* __restrict__ O) {
    int idx = blockIdx.x * 256 + threadIdx.x;
    int c = idx & 255;
    O[idx] = X[idx] * g_sc2[c] + g_sh2[c];
}

// vt[b] = sum_nodes hin + vn[b]
__global__ void k_vt(const float* __restrict__ vnp, int vnstride) {
    int b = blockIdx.x, c = threadIdx.x;
    const float* base = g_hin + (size_t)b*NPG*EMB + c;
    float s = 0.f;
    for (int r = 0; r < NPG; r++) s += base[(size_t)r*EMB];
    g_vt[b*EMB + c] = s + vnp[b*vnstride + c];
}

// ------------------------------ host orchestration --------------------------
extern "C" void kernel_launch(void* const* d_in, const int* in_sizes, int n_in,
                              void* d_out, int out_size) {
    const int ab = n_in - 19;
    const int*   atom_idx = (const int*)  d_in[0];
    const int*   lei      = (const int*)  d_in[1];
    const int*   eai      = (const int*)  d_in[2];
    const float* atom_emb = (const float*)d_in[ab + 0];
    const float* bemb_h   = (const float*)d_in[ab + 1];
    const float* elin_w   = (const float*)d_in[ab + 2];
    const float* elin_b   = (const float*)d_in[ab + 3];
    const float* bemb_l   = (const float*)d_in[ab + 4];
    const float* gin_eps  = (const float*)d_in[ab + 5];
    const float* mlp_w1   = (const float*)d_in[ab + 6];
    const float* mlp_b1   = (const float*)d_in[ab + 7];
    const float* bn_g     = (const float*)d_in[ab + 8];
    const float* bn_b     = (const float*)d_in[ab + 9];
    const float* mlp_w2   = (const float*)d_in[ab + 10];
    const float* mlp_b2   = (const float*)d_in[ab + 11];
    const float* obn_g    = (const float*)d_in[ab + 12];
    const float* obn_b    = (const float*)d_in[ab + 13];
    const float* vn_emb   = (const float*)d_in[ab + 14];
    const float* vn_w1    = (const float*)d_in[ab + 15];
    const float* vn_b1    = (const float*)d_in[ab + 16];
    const float* vn_w2    = (const float*)d_in[ab + 17];
    const float* vn_b2    = (const float*)d_in[ab + 18];
    float* out = (float*)d_out;

    float *p_x1, *p_x2, *p_z, *p_t, *p_h2, *p_h, *p_vt, *p_vh, *p_vn, *p_A;
    float *p_sum, *p_sq, *p_sc1, *p_sh1, *p_sc2, *p_sh2;
    cudaGetSymbolAddress((void**)&p_x1, g_x1);
    cudaGetSymbolAddress((void**)&p_x2, g_x2);
    cudaGetSymbolAddress((void**)&p_z,  g_z);
    cudaGetSymbolAddress((void**)&p_t,  g_t);
    cudaGetSymbolAddress((void**)&p_h2, g_h2);
    cudaGetSymbolAddress((void**)&p_h,  g_h);
    cudaGetSymbolAddress((void**)&p_vt, g_vt);
    cudaGetSymbolAddress((void**)&p_vh, g_vh);
    cudaGetSymbolAddress((void**)&p_vn, g_vn);
    cudaGetSymbolAddress((void**)&p_A,  g_A);
    cudaGetSymbolAddress((void**)&p_sum, g_sum);
    cudaGetSymbolAddress((void**)&p_sq,  g_sq);
    cudaGetSymbolAddress((void**)&p_sc1, g_sc1);
    cudaGetSymbolAddress((void**)&p_sh1, g_sh1);
    cudaGetSymbolAddress((void**)&p_sc2, g_sc2);
    cudaGetSymbolAddress((void**)&p_sh2, g_sh2);

    const int NE = NTOT*EMB/256;

    // ---- setup ----
    k_zero<<<(int)(((size_t)BG*NPG*NPG + 255)/256), 256>>>();
    k_ewt<<<1, 512>>>(bemb_h, elin_w, elin_b);
    k_scatter<<<ETOT/256, 256>>>(lei, eai);
    k_adjfin<<<BG, 256>>>();
    k_scan<<<BG, 256>>>();
    k_csrfill<<<ETOT/256, 256>>>(lei, eai);
    k_gather<<<NE, 256>>>(atom_idx, atom_emb);

    // ---- propagation: h = 0.25*(f + Af + A^2 f + A^3 f) ----
    dim3 pgrid(NPG/BN, NPG/BM, BG);
    long sA = (long)NPG*NPG, sX = (long)NPG*EMB;
    k_mma<<<pgrid, 256>>>(p_A, p_x1, nullptr, p_x2, p_h, NPG, EMB, NPG, 2, sA, sX, sX,
                          nullptr, nullptr, nullptr, nullptr);
    k_mma<<<pgrid, 256>>>(p_A, p_x2, nullptr, p_x1, p_h, NPG, EMB, NPG, 2, sA, sX, sX,
                          nullptr, nullptr, nullptr, nullptr);
    k_mma<<<pgrid, 256>>>(p_A, p_x1, nullptr, p_x2, p_h, NPG, EMB, NPG, 2, sA, sX, sX,
                          nullptr, nullptr, nullptr, nullptr);

    // ---- GIN + virtual-node stack ----
    const float* src = p_h;           // layer-0 node features
    const float* sc2 = nullptr;       // bn2 params of previous layer
    const float* sh2 = nullptr;
    const float* vnp = vn_emb;        // layer-0 vn (broadcast)
    int vnstride = 0;

    for (int l = 0; l < NL; l++) {
        // fused: (bn2+relu of prev layer) + vn add + hin store + GIN aggregate
        k_agg<<<NTOT, 256>>>(src, sc2, sh2,
                             bemb_l + (size_t)l*16*EMB, gin_eps + l, vnp, vnstride);

        // GEMM1: t = z @ w1 + b1  (stats fused)
        k_zstat<<<2, 256>>>();
        k_mma<<<dim3(2*EMB/BN, NTOT/BM, 1), 256>>>(
            p_z, mlp_w1 + (size_t)l*EMB*2*EMB, mlp_b1 + (size_t)l*2*EMB,
            p_t, nullptr, NTOT, 2*EMB, EMB, 0, 0, 0, 0,
            nullptr, nullptr, p_sum, p_sq);
        k_bnfin<<<2, 256>>>(bn_g + (size_t)l*2*EMB, bn_b + (size_t)l*2*EMB,
                            p_sc1, p_sh1, 2*EMB);

        // GEMM2: h2 = relu(bn1(t)) @ w2 + b2   (bn1+relu fused in A-load, stats fused)
        k_zstat<<<2, 256>>>();
        k_mma<<<dim3(EMB/BN, NTOT/BM, 1), 256>>>(
            p_t, mlp_w2 + (size_t)l*2*EMB*EMB, mlp_b2 + (size_t)l*EMB,
            p_h2, nullptr, NTOT, EMB, 2*EMB, 0, 0, 0, 0,
            p_sc1, p_sh1, p_sum, p_sq);
        k_bnfin<<<1, 256>>>(obn_g + (size_t)l*EMB, obn_b + (size_t)l*EMB,
                            p_sc2, p_sh2, EMB);

        if (l < NL - 1) {
            k_vt<<<BG, 256>>>(vnp, vnstride);
            k_mma<<<dim3(2*EMB/BN, BG/BM, 1), 256>>>(
                p_vt, vn_w1 + (size_t)l*EMB*2*EMB, vn_b1 + (size_t)l*2*EMB,
                p_vh, nullptr, BG, 2*EMB, EMB, 1, 0, 0, 0,
                nullptr, nullptr, nullptr, nullptr);
            k_mma<<<dim3(EMB/BN, BG/BM, 1), 256>>>(
                p_vh, vn_w2 + (size_t)l*2*EMB*EMB, vn_b2 + (size_t)l*EMB,
                p_vn, nullptr, BG, EMB, 2*EMB, 1, 0, 0, 0,
                nullptr, nullptr, nullptr, nullptr);
        }

        src = p_h2;
        sc2 = p_sc2; sh2 = p_sh2;
        vnp = p_vn; vnstride = EMB;
    }

    // final: out = bn2(h2), no relu
    k_bnout<<<NE, 256>>>(p_h2, out);
    (void)in_sizes; (void)out_size;
}

// round 6
// speedup vs baseline: 1.2778x; 1.2778x over previous
#include <cuda_runtime.h>
#include <cuda_bf16.h>
#include <math.h>

#define BG   128
#define NPG  256
#define EPG  2048
#define EMB  256
#define NL   5
#define NTOT (BG*NPG)     // 32768 nodes
#define ETOT (BG*EPG)     // 262144 edges

typedef unsigned long long ull;

// ------------------------------ scratch (device globals; no allocs) ---------
__device__ ull   g_pack[(size_t)BG*NPG*NPG];   // packed last-write-wins adjacency
__device__ float g_A   [(size_t)BG*NPG*NPG];   // normalized adjacency
__device__ float g_h  [NTOT*EMB];
__device__ float g_x1 [NTOT*EMB];
__device__ float g_x2 [NTOT*EMB];
__device__ float g_hin[NTOT*EMB];
__device__ float g_z  [NTOT*EMB];
__device__ float g_t  [NTOT*2*EMB];
__device__ float g_h2 [NTOT*EMB];
__device__ float g_vn [BG*EMB];
__device__ float g_vt [BG*EMB];
__device__ float g_vh [BG*2*EMB];
__device__ float g_ewt[16];
__device__ int   g_deg[NTOT];
__device__ int   g_ptr[NTOT];
__device__ int   g_cur[NTOT];
__device__ int   g_csrc[ETOT];
__device__ int   g_cea [ETOT];
__device__ float g_sum[2*EMB];
__device__ float g_sq [2*EMB];
__device__ float g_scale[2*EMB];
__device__ float g_shift[2*EMB];

// ------------------------------ setup kernels -------------------------------
__global__ void k_zero() {
    size_t i = (size_t)blockIdx.x * 256 + threadIdx.x;
    if (i < (size_t)BG*NPG*NPG) g_pack[i] = 0ull;
    if (i < NTOT) g_deg[i] = 0;
}

__global__ void k_ewt(const float* __restrict__ bh, const float* __restrict__ w,
                      const float* __restrict__ b) {
    int warp = threadIdx.x >> 5, lane = threadIdx.x & 31;
    if (warp < 16) {
        float v = bh[warp*64 + lane] * w[lane] + bh[warp*64 + 32 + lane] * w[32 + lane];
        #pragma unroll
        for (int o = 16; o; o >>= 1) v += __shfl_down_sync(0xffffffffu, v, o);
        if (lane == 0) g_ewt[warp] = 1.f / (1.f + expf(-(v + b[0])));
    }
}

__global__ void k_scatter(const int* __restrict__ lei, const int* __restrict__ eai) {
    int idx = blockIdx.x * 256 + threadIdx.x;
    if (idx >= ETOT) return;
    int b = idx / EPG, k = idx - b * EPG;
    int s = lei[(size_t)b*2*EPG + k];
    int d = lei[(size_t)b*2*EPG + EPG + k];
    int t = eai[idx];
    float w = g_ewt[t];
    ull key = ((ull)(k + 1) << 32) | (ull)__float_as_uint(w);
    atomicMax(&g_pack[(size_t)b*NPG*NPG + (size_t)s*NPG + d], key);
    atomicAdd(&g_deg[b*NPG + d], 1);
}

__global__ void k_adjfin() {
    int g = blockIdx.x, tid = threadIdx.x;
    __shared__ float cs[NPG], rs[NPG];
    const ull* P = g_pack + (size_t)g*NPG*NPG;
    float*     A = g_A    + (size_t)g*NPG*NPG;
    float c = 0.f;
    for (int i = 0; i < NPG; i++) {
        ull p = P[(size_t)i*NPG + tid];
        float v = p ? __uint_as_float((unsigned)(p & 0xffffffffu)) : 0.f;
        if (i == tid) v += 1.f;
        A[(size_t)i*NPG + tid] = v;
        c += v;
    }
    cs[tid] = rsqrtf(c);
    __syncthreads();
    float r = 0.f;
    for (int j = 0; j < NPG; j++) r += A[(size_t)tid*NPG + j];
    rs[tid] = rsqrtf(r);
    __syncthreads();
    for (int i = 0; i < NPG; i++)
        A[(size_t)i*NPG + tid] *= cs[i] * rs[tid];
}

__global__ void k_scan() {
    int g = blockIdx.x, tid = threadIdx.x;
    __shared__ int s[NPG];
    int d = g_deg[g*NPG + tid];
    s[tid] = d;
    __syncthreads();
    for (int off = 1; off < NPG; off <<= 1) {
        int v = (tid >= off) ? s[tid - off] : 0;
        __syncthreads();
        s[tid] += v;
        __syncthreads();
    }
    int excl = s[tid] - d;
    g_ptr[g*NPG + tid] = g*EPG + excl;
    g_cur[g*NPG + tid] = g*EPG + excl;
}

__global__ void k_csrfill(const int* __restrict__ lei, const int* __restrict__ eai) {
    int idx = blockIdx.x * 256 + threadIdx.x;
    if (idx >= ETOT) return;
    int b = idx / EPG, k = idx - b * EPG;
    int s = lei[(size_t)b*2*EPG + k];
    int d = lei[(size_t)b*2*EPG + EPG + k];
    int pos = atomicAdd(&g_cur[b*NPG + d], 1);
    g_csrc[pos] = b*NPG + s;
    g_cea [pos] = eai[idx];
}

__global__ void k_gather(const int* __restrict__ aidx, const float* __restrict__ aemb) {
    int idx = blockIdx.x * 256 + threadIdx.x;
    int n = idx >> 8, c = idx & 255;
    float v = aemb[aidx[n]*EMB + c];
    g_h[idx]  = v;
    g_x1[idx] = v;
}

// ------------------------------ bf16x3 tensor-core GEMM ---------------------
// fp32-accurate: x = hi + lo (bf16), A@B ~= Ah@Bh + Ah@Bl + Al@Bh
// CTA tile 128x64x16, 8 warps (4x2), warp tile 32x32, mma.m16n8k16.bf16
// smem in FRAGMENT-ORDER layout: a-frag = 1 LDS.128, b-frag = 1 LDS.64
#define BM 128
#define BN 64
#define BK 16

__device__ __forceinline__ unsigned pack2(float e, float o) {
    unsigned r;
    asm("cvt.rn.bf16x2.f32 %0, %1, %2;" : "=r"(r) : "f"(o), "f"(e));
    return r;
}
__device__ __forceinline__ void split2(float e, float o, unsigned &hi, unsigned &lo) {
    float he = __bfloat162float(__float2bfloat16(e));
    float ho = __bfloat162float(__float2bfloat16(o));
    hi = pack2(e, o);
    lo = pack2(e - he, o - ho);
}

#define MMA_BF16(c, a, b)                                                     \
    asm volatile(                                                             \
        "mma.sync.aligned.m16n8k16.row.col.f32.bf16.bf16.f32 "                \
        "{%0,%1,%2,%3}, {%4,%5,%6,%7}, {%8,%9}, {%0,%1,%2,%3};\n"             \
        : "+f"((c)[0]), "+f"((c)[1]), "+f"((c)[2]), "+f"((c)[3])              \
        : "r"((a)[0]), "r"((a)[1]), "r"((a)[2]), "r"((a)[3]),                 \
          "r"((b)[0]), "r"((b)[1]))

// mode: 0 = C=acc+bias, 1 = C=relu(acc+bias), 2 = C=acc, Y+=acc (no bias)
__global__ void __launch_bounds__(256)
k_mma(const float* __restrict__ A, const float* __restrict__ B,
      const float* __restrict__ bias, float* __restrict__ C, float* __restrict__ Y,
      int M, int N, int K, int mode,
      long strideA, long strideB, long strideC) {
    A += (size_t)blockIdx.z * strideA;
    B += (size_t)blockIdx.z * strideB;
    C += (size_t)blockIdx.z * strideC;
    if (Y) Y += (size_t)blockIdx.z * strideC;

    // A fragment layout: [m16(8)][gid(8)][tig^xw(4)][w(4)]  (128 words / m16 block)
    // B fragment layout: [n8(8)][gid(8)][tig(4)][w(2)], n8-stride padded to 68
    __shared__ __align__(16) unsigned AhF[1024], AlF[1024];
    __shared__ __align__(16) unsigned BhF[8*68], BlF[8*68];

    int tid  = threadIdx.x;
    int lane = tid & 31, warp = tid >> 5;
    int wm = warp >> 1, wn = warp & 1;          // 4x2 warp grid
    int bm = blockIdx.y * BM, bn = blockIdx.x * BN;

    // ---- writer indices ----
    int a_r0 = tid >> 2;             // rows a_r0 and a_r0+64
    int a_c  = (tid & 3) << 2;       // k offset (4 floats)
    int a_k2 = (tid & 3) << 1;       // first packed k2 word
    int gw   = a_r0 & 7;             // gid of written rows (same for both h)
    int hf   = (a_r0 >> 3) & 1;      // half bit (same for both h: +64 = +4 m16)
    int m16a = a_r0 >> 4;            // m16 of h=0 row; h=1 adds 4
    int xw   = (gw >> 1) & 3;        // write-side XOR swizzle
    int tw0  = a_k2 & 3,      w0b = ((a_k2 >> 2) << 1) + hf;
    int tw1  = (a_k2 + 1) & 3, w1b = (((a_k2 + 1) >> 2) << 1) + hf;
    int aoff0 = gw*16 + ((tw0 ^ xw) << 2) + w0b;
    int aoff1 = gw*16 + ((tw1 ^ xw) << 2) + w1b;

    int b_k2 = tid >> 5;             // 0..7 (constant per warp)
    int b_n  = lane << 1;            // 0..62
    int tigb = b_k2 & 3, wbb = b_k2 >> 2;
    int bidx0 = ((b_n >> 3) * 68) + ((b_n & 7) << 3) + tigb*2 + wbb;
    int bidx1 = (((b_n+1) >> 3) * 68) + (((b_n+1) & 7) << 3) + tigb*2 + wbb;

    // ---- reader indices ----
    int gid = lane >> 2, tig = lane & 3;
    int xr  = (gid >> 1) & 3;
    int aro = gid*16 + ((tig ^ xr) << 2);    // + m16r*128
    int bro = gid*8 + tig*2;                 // + n8*68

    float acc[2][4][4];
    #pragma unroll
    for (int i = 0; i < 2; i++)
        #pragma unroll
        for (int j = 0; j < 4; j++)
            #pragma unroll
            for (int r = 0; r < 4; r++) acc[i][j][r] = 0.f;

    for (int k0 = 0; k0 < K; k0 += BK) {
        // ---- load + split A tile 128x16 ----
        #pragma unroll
        for (int h = 0; h < 2; h++) {
            int r = a_r0 + h*64;
            int base = (m16a + 4*h) * 128;
            float4 v = *reinterpret_cast<const float4*>(A + (size_t)(bm + r)*K + k0 + a_c);
            unsigned hi0, lo0, hi1, lo1;
            split2(v.x, v.y, hi0, lo0);
            split2(v.z, v.w, hi1, lo1);
            AhF[base + aoff0] = hi0;  AlF[base + aoff0] = lo0;
            AhF[base + aoff1] = hi1;  AlF[base + aoff1] = lo1;
        }
        // ---- load + split B tile 16x64 ----
        {
            const float* Bp = B + (size_t)(k0 + 2*b_k2)*N + bn + b_n;
            float2 ve = *reinterpret_cast<const float2*>(Bp);
            float2 vo = *reinterpret_cast<const float2*>(Bp + N);
            unsigned hi0, lo0, hi1, lo1;
            split2(ve.x, vo.x, hi0, lo0);
            split2(ve.y, vo.y, hi1, lo1);
            BhF[bidx0] = hi0;  BlF[bidx0] = lo0;
            BhF[bidx1] = hi1;  BlF[bidx1] = lo1;
        }
        __syncthreads();

        // ---- vectorized fragment loads ----
        unsigned ah[2][4], al[2][4], bh[4][2], bl[4][2];
        #pragma unroll
        for (int mf = 0; mf < 2; mf++) {
            int ao = (wm*2 + mf)*128 + aro;
            uint4 th = *reinterpret_cast<const uint4*>(&AhF[ao]);
            uint4 tl = *reinterpret_cast<const uint4*>(&AlF[ao]);
            ah[mf][0] = th.x; ah[mf][1] = th.y; ah[mf][2] = th.z; ah[mf][3] = th.w;
            al[mf][0] = tl.x; al[mf][1] = tl.y; al[mf][2] = tl.z; al[mf][3] = tl.w;
        }
        #pragma unroll
        for (int nf = 0; nf < 4; nf++) {
            int bo = (wn*4 + nf)*68 + bro;
            uint2 th = *reinterpret_cast<const uint2*>(&BhF[bo]);
            uint2 tl = *reinterpret_cast<const uint2*>(&BlF[bo]);
            bh[nf][0] = th.x; bh[nf][1] = th.y;
            bl[nf][0] = tl.x; bl[nf][1] = tl.y;
        }

        // ---- 3-product split MMA ----
        #pragma unroll
        for (int mf = 0; mf < 2; mf++)
            #pragma unroll
            for (int nf = 0; nf < 4; nf++) {
                float* c = acc[mf][nf];
                MMA_BF16(c, ah[mf], bl[nf]);
                MMA_BF16(c, al[mf], bh[nf]);
                MMA_BF16(c, ah[mf], bh[nf]);
            }
        __syncthreads();
    }

    // ---- epilogue ----
    int gid2 = lane >> 2, tig2 = lane & 3;
    #pragma unroll
    for (int mf = 0; mf < 2; mf++) {
        #pragma unroll
        for (int nf = 0; nf < 4; nf++) {
            int r0 = bm + wm*32 + mf*16 + gid2;
            int c0 = bn + wn*32 + nf*8 + 2*tig2;
            float* c = acc[mf][nf];
            #pragma unroll
            for (int half = 0; half < 2; half++) {
                int r = r0 + half*8;
                float v0 = c[half*2+0], v1 = c[half*2+1];
                if (mode != 2) {
                    v0 += bias[c0]; v1 += bias[c0+1];
                    if (mode == 1) { v0 = fmaxf(v0, 0.f); v1 = fmaxf(v1, 0.f); }
                    *reinterpret_cast<float2*>(C + (size_t)r*N + c0) = make_float2(v0, v1);
                } else {
                    *reinterpret_cast<float2*>(C + (size_t)r*N + c0) = make_float2(v0, v1);
                    float2* y = reinterpret_cast<float2*>(Y + (size_t)r*N + c0);
                    float2 yo = *y;
                    yo.x += v0; yo.y += v1;
                    *y = yo;
                }
            }
        }
    }
}

__global__ void k_scale() {
    int idx = blockIdx.x * 256 + threadIdx.x;
    g_h[idx] *= 0.25f;    // /(order+1), order=3
}

// ------------------------------ GIN layer kernels ---------------------------
__global__ void k_initvn(const float* __restrict__ vemb) {
    int idx = blockIdx.x * 256 + threadIdx.x;
    g_vn[idx] = vemb[idx & 255];
}

__global__ void k_addvn() {
    int idx = blockIdx.x * 256 + threadIdx.x;
    int b = idx >> 16;
    int c = idx & 255;
    float v = g_h[idx] + g_vn[b*EMB + c];
    g_h[idx] = v;
    g_hin[idx] = v;
}

__global__ void k_agg(const float* __restrict__ eembL, const float* __restrict__ epsp) {
    int n = blockIdx.x, c = threadIdx.x;
    int start = g_ptr[n], deg = g_deg[n];
    float val = 0.f;
    for (int k = 0; k < deg; k++) {
        int s = g_csrc[start + k];
        int t = g_cea [start + k];
        float m = g_h[(size_t)s*EMB + c] + eembL[t*EMB + c];
        val += fmaxf(m, 0.f);
    }
    float eps = *epsp;
    g_z[(size_t)n*EMB + c] = (1.f + eps) * g_h[(size_t)n*EMB + c] + val;
}

// ------------------------------ batchnorm -----------------------------------
__global__ void k_zstat() {
    int i = blockIdx.x * 256 + threadIdx.x;
    if (i < 2*EMB) { g_sum[i] = 0.f; g_sq[i] = 0.f; }
}

__global__ void k_bnstats(const float* __restrict__ X, int C) {
    int r0 = blockIdx.x * 128;
    for (int c = threadIdx.x; c < C; c += 256) {
        float s = 0.f, q = 0.f;
        for (int r = 0; r < 128; r++) {
            float v = X[(size_t)(r0 + r)*C + c];
            s += v; q += v * v;
        }
        atomicAdd(&g_sum[c], s);
        atomicAdd(&g_sq[c], q);
    }
}

__global__ void k_bnfin(const float* __restrict__ g, const float* __restrict__ b, int C) {
    int c = blockIdx.x * 256 + threadIdx.x;
    if (c >= C) return;
    float mu  = g_sum[c] * (1.f / NTOT);
    float var = g_sq[c] * (1.f / NTOT) - mu * mu;
    float sc  = g[c] * rsqrtf(var + 1e-5f);
    g_scale[c] = sc;
    g_shift[c] = b[c] - mu * sc;
}

__global__ void k_bnapply(const float* __restrict__ X, float* __restrict__ O,
                          int cmask, int act) {
    int idx = blockIdx.x * 256 + threadIdx.x;
    int c = idx & cmask;
    float v = X[idx] * g_scale[c] + g_shift[c];
    if (act) v = fmaxf(v, 0.f);
    O[idx] = v;
}

__global__ void k_vt() {
    int b = blockIdx.x, c = threadIdx.x;
    const float* base = g_hin + (size_t)b*NPG*EMB + c;
    float s = 0.f;
    for (int r = 0; r < NPG; r++) s += base[(size_t)r*EMB];
    g_vt[b*EMB + c] = s + g_vn[b*EMB + c];
}

// ------------------------------ host orchestration --------------------------
extern "C" void kernel_launch(void* const* d_in, const int* in_sizes, int n_in,
                              void* d_out, int out_size) {
    const int ab = n_in - 19;
    const int*   atom_idx = (const int*)  d_in[0];
    const int*   lei      = (const int*)  d_in[1];
    const int*   eai      = (const int*)  d_in[2];
    const float* atom_emb = (const float*)d_in[ab + 0];
    const float* bemb_h   = (const float*)d_in[ab + 1];
    const float* elin_w   = (const float*)d_in[ab + 2];
    const float* elin_b   = (const float*)d_in[ab + 3];
    const float* bemb_l   = (const float*)d_in[ab + 4];
    const float* gin_eps  = (const float*)d_in[ab + 5];
    const float* mlp_w1   = (const float*)d_in[ab + 6];
    const float* mlp_b1   = (const float*)d_in[ab + 7];
    const float* bn_g     = (const float*)d_in[ab + 8];
    const float* bn_b     = (const float*)d_in[ab + 9];
    const float* mlp_w2   = (const float*)d_in[ab + 10];
    const float* mlp_b2   = (const float*)d_in[ab + 11];
    const float* obn_g    = (const float*)d_in[ab + 12];
    const float* obn_b    = (const float*)d_in[ab + 13];
    const float* vn_emb   = (const float*)d_in[ab + 14];
    const float* vn_w1    = (const float*)d_in[ab + 15];
    const float* vn_b1    = (const float*)d_in[ab + 16];
    const float* vn_w2    = (const float*)d_in[ab + 17];
    const float* vn_b2    = (const float*)d_in[ab + 18];
    float* out = (float*)d_out;

    float *p_x1, *p_x2, *p_z, *p_t, *p_h2, *p_h, *p_vt, *p_vh, *p_vn, *p_A;
    cudaGetSymbolAddress((void**)&p_x1, g_x1);
    cudaGetSymbolAddress((void**)&p_x2, g_x2);
    cudaGetSymbolAddress((void**)&p_z,  g_z);
    cudaGetSymbolAddress((void**)&p_t,  g_t);
    cudaGetSymbolAddress((void**)&p_h2, g_h2);
    cudaGetSymbolAddress((void**)&p_h,  g_h);
    cudaGetSymbolAddress((void**)&p_vt, g_vt);
    cudaGetSymbolAddress((void**)&p_vh, g_vh);
    cudaGetSymbolAddress((void**)&p_vn, g_vn);
    cudaGetSymbolAddress((void**)&p_A,  g_A);

    const int NE = NTOT*EMB/256;

    // ---- setup ----
    k_zero<<<(int)(((size_t)BG*NPG*NPG + 255)/256), 256>>>();
    k_ewt<<<1, 512>>>(bemb_h, elin_w, elin_b);
    k_scatter<<<ETOT/256, 256>>>(lei, eai);
    k_adjfin<<<BG, 256>>>();
    k_scan<<<BG, 256>>>();
    k_csrfill<<<ETOT/256, 256>>>(lei, eai);
    k_gather<<<NE, 256>>>(atom_idx, atom_emb);

    // ---- propagation: y = (f + Af + A^2 f + A^3 f) / 4 ----
    dim3 pgrid(NPG/BN, NPG/BM, BG);
    long sA = (long)NPG*NPG, sX = (long)NPG*EMB;
    k_mma<<<pgrid, 256>>>(p_A, p_x1, nullptr, p_x2, p_h, NPG, EMB, NPG, 2, sA, sX, sX);
    k_mma<<<pgrid, 256>>>(p_A, p_x2, nullptr, p_x1, p_h, NPG, EMB, NPG, 2, sA, sX, sX);
    k_mma<<<pgrid, 256>>>(p_A, p_x1, nullptr, p_x2, p_h, NPG, EMB, NPG, 2, sA, sX, sX);
    k_scale<<<NE, 256>>>();

    k_initvn<<<BG*EMB/256, 256>>>(vn_emb);

    // ---- GIN + virtual-node stack ----
    for (int l = 0; l < NL; l++) {
        k_addvn<<<NE, 256>>>();
        k_agg<<<NTOT, 256>>>(bemb_l + (size_t)l*16*EMB, gin_eps + l);

        // z @ w1 + b1 -> t [N, 512]
        k_mma<<<dim3(2*EMB/BN, NTOT/BM, 1), 256>>>(
            p_z, mlp_w1 + (size_t)l*EMB*2*EMB, mlp_b1 + (size_t)l*2*EMB,
            p_t, nullptr, NTOT, 2*EMB, EMB, 0, 0, 0, 0);
        // BN1 + relu (in place)
        k_zstat<<<2, 256>>>();
        k_bnstats<<<NTOT/128, 256>>>(p_t, 2*EMB);
        k_bnfin<<<2, 256>>>(bn_g + (size_t)l*2*EMB, bn_b + (size_t)l*2*EMB, 2*EMB);
        k_bnapply<<<NTOT*2*EMB/256, 256>>>(p_t, p_t, 2*EMB - 1, 1);

        // t @ w2 + b2 -> h2 [N, 256]
        k_mma<<<dim3(EMB/BN, NTOT/BM, 1), 256>>>(
            p_t, mlp_w2 + (size_t)l*2*EMB*EMB, mlp_b2 + (size_t)l*EMB,
            p_h2, nullptr, NTOT, EMB, 2*EMB, 0, 0, 0, 0);
        // BN2 (+relu except last layer); last layer writes straight to out
        k_zstat<<<2, 256>>>();
        k_bnstats<<<NTOT/128, 256>>>(p_h2, EMB);
        k_bnfin<<<1, 256>>>(obn_g + (size_t)l*EMB, obn_b + (size_t)l*EMB, EMB);
        if (l < NL - 1)
            k_bnapply<<<NE, 256>>>(p_h2, p_h, EMB - 1, 1);
        else
            k_bnapply<<<NE, 256>>>(p_h2, out, EMB - 1, 0);

        // virtual node update
        if (l < NL - 1) {
            k_vt<<<BG, 256>>>();
            k_mma<<<dim3(2*EMB/BN, BG/BM, 1), 256>>>(
                p_vt, vn_w1 + (size_t)l*EMB*2*EMB, vn_b1 + (size_t)l*2*EMB,
                p_vh, nullptr, BG, 2*EMB, EMB, 1, 0, 0, 0);
            k_mma<<<dim3(EMB/BN, BG/BM, 1), 256>>>(
                p_vh, vn_w2 + (size_t)l*2*EMB*EMB, vn_b2 + (size_t)l*EMB,
                p_vn, nullptr, BG, EMB, 2*EMB, 1, 0, 0, 0);
        }
    }

    (void)in_sizes; (void)out_size;
}

// round 7
// speedup vs baseline: 1.4413x; 1.1279x over previous
#include <cuda_runtime.h>
#include <cuda_bf16.h>
#include <math.h>

#define BG   128
#define NPG  256
#define EPG  2048
#define EMB  256
#define NL   5
#define NTOT (BG*NPG)     // 32768 nodes
#define ETOT (BG*EPG)     // 262144 edges

typedef unsigned long long ull;
typedef __nv_bfloat16 bf16;

// ------------------------------ scratch (device globals; no allocs) ---------
__device__ ull   g_pack[(size_t)BG*NPG*NPG];
__device__ float g_A   [(size_t)BG*NPG*NPG];
__device__ float g_h  [NTOT*EMB];
__device__ float g_hin[NTOT*EMB];
__device__ float g_t  [NTOT*2*EMB];
__device__ float g_h2 [NTOT*EMB];
__device__ float g_vn [BG*EMB];
__device__ float g_ewt[16];
__device__ int   g_deg[NTOT];
__device__ int   g_ptr[NTOT];
__device__ int   g_cur[NTOT];
__device__ int   g_csrc[ETOT];
__device__ int   g_cea [ETOT];
__device__ float g_sum[2*EMB];
__device__ float g_sq [2*EMB];
__device__ float g_scale[2*EMB];
__device__ float g_shift[2*EMB];

// bf16 hi/lo planes (GEMM operands)
__device__ __align__(16) bf16 g_Ahp[(size_t)BG*NPG*NPG], g_Alp[(size_t)BG*NPG*NPG];
__device__ __align__(16) bf16 g_x1h[NTOT*EMB], g_x1l[NTOT*EMB];
__device__ __align__(16) bf16 g_x2h[NTOT*EMB], g_x2l[NTOT*EMB];
__device__ __align__(16) bf16 g_zh [NTOT*EMB], g_zl [NTOT*EMB];
__device__ __align__(16) bf16 g_th [NTOT*2*EMB], g_tl [NTOT*2*EMB];
__device__ __align__(16) bf16 g_vth[BG*EMB],   g_vtl[BG*EMB];
__device__ __align__(16) bf16 g_vhh[BG*2*EMB], g_vhl[BG*2*EMB];
__device__ __align__(16) bf16 g_w1h[NL*EMB*2*EMB],  g_w1l[NL*EMB*2*EMB];
__device__ __align__(16) bf16 g_w2h[NL*2*EMB*EMB],  g_w2l[NL*2*EMB*EMB];
__device__ __align__(16) bf16 g_u1h[(NL-1)*EMB*2*EMB], g_u1l[(NL-1)*EMB*2*EMB];
__device__ __align__(16) bf16 g_u2h[(NL-1)*2*EMB*EMB], g_u2l[(NL-1)*2*EMB*EMB];

__device__ __forceinline__ void splitw(float v, bf16* __restrict__ h,
                                       bf16* __restrict__ l, size_t i) {
    bf16 hv = __float2bfloat16(v);
    h[i] = hv;
    l[i] = __float2bfloat16(v - __bfloat162float(hv));
}

// ------------------------------ setup kernels -------------------------------
__global__ void k_zero() {
    size_t i = (size_t)blockIdx.x * 256 + threadIdx.x;
    if (i < (size_t)BG*NPG*NPG) g_pack[i] = 0ull;
    if (i < NTOT) g_deg[i] = 0;
}

__global__ void k_ewt(const float* __restrict__ bh, const float* __restrict__ w,
                      const float* __restrict__ b) {
    int warp = threadIdx.x >> 5, lane = threadIdx.x & 31;
    if (warp < 16) {
        float v = bh[warp*64 + lane] * w[lane] + bh[warp*64 + 32 + lane] * w[32 + lane];
        #pragma unroll
        for (int o = 16; o; o >>= 1) v += __shfl_down_sync(0xffffffffu, v, o);
        if (lane == 0) g_ewt[warp] = 1.f / (1.f + expf(-(v + b[0])));
    }
}

__global__ void k_scatter(const int* __restrict__ lei, const int* __restrict__ eai) {
    int idx = blockIdx.x * 256 + threadIdx.x;
    if (idx >= ETOT) return;
    int b = idx / EPG, k = idx - b * EPG;
    int s = lei[(size_t)b*2*EPG + k];
    int d = lei[(size_t)b*2*EPG + EPG + k];
    int t = eai[idx];
    float w = g_ewt[t];
    ull key = ((ull)(k + 1) << 32) | (ull)__float_as_uint(w);
    atomicMax(&g_pack[(size_t)b*NPG*NPG + (size_t)s*NPG + d], key);
    atomicAdd(&g_deg[b*NPG + d], 1);
}

__global__ void k_adjfin() {
    int g = blockIdx.x, tid = threadIdx.x;
    __shared__ float cs[NPG], rs[NPG];
    const ull* P = g_pack + (size_t)g*NPG*NPG;
    float*     A = g_A    + (size_t)g*NPG*NPG;
    float c = 0.f;
    for (int i = 0; i < NPG; i++) {
        ull p = P[(size_t)i*NPG + tid];
        float v = p ? __uint_as_float((unsigned)(p & 0xffffffffu)) : 0.f;
        if (i == tid) v += 1.f;
        A[(size_t)i*NPG + tid] = v;
        c += v;
    }
    cs[tid] = rsqrtf(c);
    __syncthreads();
    float r = 0.f;
    for (int j = 0; j < NPG; j++) r += A[(size_t)tid*NPG + j];
    rs[tid] = rsqrtf(r);
    __syncthreads();
    size_t base = (size_t)g*NPG*NPG;
    for (int i = 0; i < NPG; i++) {
        float v = A[(size_t)i*NPG + tid] * cs[i] * rs[tid];
        splitw(v, g_Ahp, g_Alp, base + (size_t)i*NPG + tid);
    }
}

__global__ void k_scan() {
    int g = blockIdx.x, tid = threadIdx.x;
    __shared__ int s[NPG];
    int d = g_deg[g*NPG + tid];
    s[tid] = d;
    __syncthreads();
    for (int off = 1; off < NPG; off <<= 1) {
        int v = (tid >= off) ? s[tid - off] : 0;
        __syncthreads();
        s[tid] += v;
        __syncthreads();
    }
    int excl = s[tid] - d;
    g_ptr[g*NPG + tid] = g*EPG + excl;
    g_cur[g*NPG + tid] = g*EPG + excl;
}

__global__ void k_csrfill(const int* __restrict__ lei, const int* __restrict__ eai) {
    int idx = blockIdx.x * 256 + threadIdx.x;
    if (idx >= ETOT) return;
    int b = idx / EPG, k = idx - b * EPG;
    int s = lei[(size_t)b*2*EPG + k];
    int d = lei[(size_t)b*2*EPG + EPG + k];
    int pos = atomicAdd(&g_cur[b*NPG + d], 1);
    g_csrc[pos] = b*NPG + s;
    g_cea [pos] = eai[idx];
}

__global__ void k_gather(const int* __restrict__ aidx, const float* __restrict__ aemb) {
    int idx = blockIdx.x * 256 + threadIdx.x;
    int n = idx >> 8, c = idx & 255;
    float v = aemb[aidx[n]*EMB + c];
    g_h[idx] = v;
    splitw(v, g_x1h, g_x1l, idx);
}

// one-shot weight splitter
__global__ void k_split(const float* __restrict__ w, bf16* __restrict__ h,
                        bf16* __restrict__ l, int n) {
    int i = blockIdx.x * 256 + threadIdx.x;
    if (i < n) splitw(w[i], h, l, i);
}

// ------------------------------ pipelined bf16x3 tensor GEMM ----------------
// operands pre-split to bf16 hi/lo planes; cp.async 3-stage; ldmatrix frags
#define BM 128
#define BN 64
#define APAD 40                 // bf16 row stride of A tile (80B)
#define BPAD 72                 // bf16 row stride of B tile (144B)
#define ASEG (128*APAD)         // 5120 els / plane / stage
#define BSEG (32*BPAD)          // 2304
#define BBASE (6*ASEG)
#define SMEM_BYTES ((6*ASEG + 6*BSEG)*2)   // 89088

__device__ __forceinline__ void cpa16(unsigned s, const void* g) {
    asm volatile("cp.async.cg.shared.global [%0], [%1], 16;" :: "r"(s), "l"(g));
}
#define LDSM4(r0,r1,r2,r3,a)                                                   \
    asm volatile("ldmatrix.sync.aligned.m8n8.x4.shared.b16 {%0,%1,%2,%3}, [%4];" \
        : "=r"(r0),"=r"(r1),"=r"(r2),"=r"(r3) : "r"(a))
#define LDSM4T(r0,r1,r2,r3,a)                                                  \
    asm volatile("ldmatrix.sync.aligned.m8n8.x4.trans.shared.b16 {%0,%1,%2,%3}, [%4];" \
        : "=r"(r0),"=r"(r1),"=r"(r2),"=r"(r3) : "r"(a))
#define MMA_BF16(c, a, b)                                                     \
    asm volatile(                                                             \
        "mma.sync.aligned.m16n8k16.row.col.f32.bf16.bf16.f32 "                \
        "{%0,%1,%2,%3}, {%4,%5,%6,%7}, {%8,%9}, {%0,%1,%2,%3};\n"             \
        : "+f"((c)[0]), "+f"((c)[1]), "+f"((c)[2]), "+f"((c)[3])              \
        : "r"((a)[0]), "r"((a)[1]), "r"((a)[2]), "r"((a)[3]),                 \
          "r"((b)[0]), "r"((b)[1]))

__global__ void __launch_bounds__(256, 2)
k_mma(const bf16* __restrict__ Ah, const bf16* __restrict__ Al,
      const bf16* __restrict__ Bh, const bf16* __restrict__ Bl,
      const float* __restrict__ bias,
      float* __restrict__ Cf, bf16* __restrict__ Chi, bf16* __restrict__ Clo,
      float* __restrict__ Y, int relu,
      int M, int N, int K, long sA, long sB, long sC) {
    extern __shared__ bf16 smbuf[];
    Ah += (size_t)blockIdx.z * sA;  Al += (size_t)blockIdx.z * sA;
    Bh += (size_t)blockIdx.z * sB;  Bl += (size_t)blockIdx.z * sB;
    if (Cf)  Cf  += (size_t)blockIdx.z * sC;
    if (Chi) { Chi += (size_t)blockIdx.z * sC; Clo += (size_t)blockIdx.z * sC; }
    if (Y)   Y   += (size_t)blockIdx.z * sC;

    unsigned sb = (unsigned)__cvta_generic_to_shared(smbuf);
    int tid = threadIdx.x, lane = tid & 31, warp = tid >> 5;
    int wm = warp >> 1, wn = warp & 1;          // 4x2 warps, warp tile 32x32
    int bm = blockIdx.y * BM, bn = blockIdx.x * BN;

    // cp.async copy indices
    int ar = tid >> 2, ac = (tid & 3) * 8;      // A: rows ar, ar+64; 8-el chunk
    int br = tid >> 3, bc = (tid & 7) * 8;      // B: row br (of 32), chunk
    // ldmatrix lane address parts
    int lr = lane & 15, lc = (lane >> 4) * 8;

    float acc[2][4][4];
    #pragma unroll
    for (int i = 0; i < 2; i++)
        #pragma unroll
        for (int j = 0; j < 4; j++)
            #pragma unroll
            for (int r = 0; r < 4; r++) acc[i][j][r] = 0.f;

    int niter = K / 32;

#define ISSUE(buf, kk) {                                                         \
    unsigned a0 = sb + (unsigned)(((buf)*2+0)*ASEG)*2;                            \
    unsigned a1 = sb + (unsigned)(((buf)*2+1)*ASEG)*2;                            \
    unsigned b0 = sb + (unsigned)((BBASE + ((buf)*2+0)*BSEG))*2;                  \
    unsigned b1 = sb + (unsigned)((BBASE + ((buf)*2+1)*BSEG))*2;                  \
    cpa16(a0 + (ar*APAD + ac)*2,      Ah + (size_t)(bm + ar)*K + (kk) + ac);      \
    cpa16(a0 + ((ar+64)*APAD + ac)*2, Ah + (size_t)(bm + ar + 64)*K + (kk) + ac); \
    cpa16(a1 + (ar*APAD + ac)*2,      Al + (size_t)(bm + ar)*K + (kk) + ac);      \
    cpa16(a1 + ((ar+64)*APAD + ac)*2, Al + (size_t)(bm + ar + 64)*K + (kk) + ac); \
    cpa16(b0 + (br*BPAD + bc)*2,      Bh + (size_t)((kk) + br)*N + bn + bc);      \
    cpa16(b1 + (br*BPAD + bc)*2,      Bl + (size_t)((kk) + br)*N + bn + bc);      \
}

    ISSUE(0, 0);
    asm volatile("cp.async.commit_group;");
    ISSUE(1, 32);
    asm volatile("cp.async.commit_group;");

    int cbuf = 0, ibuf = 2;
    for (int it = 0; it < niter; it++) {
        asm volatile("cp.async.wait_group 1;");
        __syncthreads();
        if (it + 2 < niter) { int kk = (it + 2) * 32; ISSUE(ibuf, kk); }
        asm volatile("cp.async.commit_group;");

        unsigned aH = sb + (unsigned)((cbuf*2+0)*ASEG)*2;
        unsigned aL = sb + (unsigned)((cbuf*2+1)*ASEG)*2;
        unsigned bH = sb + (unsigned)((BBASE + (cbuf*2+0)*BSEG))*2;
        unsigned bL = sb + (unsigned)((BBASE + (cbuf*2+1)*BSEG))*2;

        #pragma unroll
        for (int ks = 0; ks < 2; ks++) {
            unsigned ah[2][4], al[2][4], bh[4][2], bl[4][2];
            #pragma unroll
            for (int mf = 0; mf < 2; mf++) {
                unsigned off = (unsigned)(((wm*32 + mf*16 + lr)*APAD + ks*16 + lc)*2);
                LDSM4(ah[mf][0], ah[mf][1], ah[mf][2], ah[mf][3], aH + off);
                LDSM4(al[mf][0], al[mf][1], al[mf][2], al[mf][3], aL + off);
            }
            #pragma unroll
            for (int p = 0; p < 2; p++) {
                unsigned off = (unsigned)(((ks*16 + lr)*BPAD + wn*32 + p*16 + lc)*2);
                unsigned r0, r1, r2, r3;
                LDSM4T(r0, r1, r2, r3, bH + off);
                bh[2*p][0] = r0; bh[2*p][1] = r1; bh[2*p+1][0] = r2; bh[2*p+1][1] = r3;
                LDSM4T(r0, r1, r2, r3, bL + off);
                bl[2*p][0] = r0; bl[2*p][1] = r1; bl[2*p+1][0] = r2; bl[2*p+1][1] = r3;
            }
            #pragma unroll
            for (int mf = 0; mf < 2; mf++)
                #pragma unroll
                for (int nf = 0; nf < 4; nf++) {
                    float* c = acc[mf][nf];
                    MMA_BF16(c, ah[mf], bl[nf]);
                    MMA_BF16(c, al[mf], bh[nf]);
                    MMA_BF16(c, ah[mf], bh[nf]);
                }
        }
        cbuf = (cbuf == 2) ? 0 : cbuf + 1;
        ibuf = (ibuf == 2) ? 0 : ibuf + 1;
    }

    // ---- epilogue ----
    int gid = lane >> 2, tig = lane & 3;
    #pragma unroll
    for (int mf = 0; mf < 2; mf++) {
        #pragma unroll
        for (int nf = 0; nf < 4; nf++) {
            int r0 = bm + wm*32 + mf*16 + gid;
            int c0 = bn + wn*32 + nf*8 + 2*tig;
            float b0 = 0.f, b1 = 0.f;
            if (bias) { b0 = bias[c0]; b1 = bias[c0+1]; }
            float* c = acc[mf][nf];
            #pragma unroll
            for (int half = 0; half < 2; half++) {
                int r = r0 + half*8;
                float v0 = c[half*2+0] + b0, v1 = c[half*2+1] + b1;
                if (relu) { v0 = fmaxf(v0, 0.f); v1 = fmaxf(v1, 0.f); }
                if (Cf)
                    *reinterpret_cast<float2*>(Cf + (size_t)r*N + c0) = make_float2(v0, v1);
                if (Chi) {
                    bf16 h0 = __float2bfloat16(v0), h1 = __float2bfloat16(v1);
                    *reinterpret_cast<__nv_bfloat162*>(Chi + (size_t)r*N + c0) =
                        __halves2bfloat162(h0, h1);
                    bf16 l0 = __float2bfloat16(v0 - __bfloat162float(h0));
                    bf16 l1 = __float2bfloat16(v1 - __bfloat162float(h1));
                    *reinterpret_cast<__nv_bfloat162*>(Clo + (size_t)r*N + c0) =
                        __halves2bfloat162(l0, l1);
                }
                if (Y) {
                    float2* y = reinterpret_cast<float2*>(Y + (size_t)r*N + c0);
                    float2 yo = *y;
                    yo.x += v0; yo.y += v1;
                    *y = yo;
                }
            }
        }
    }
#undef ISSUE
}

__global__ void k_scale() {
    int idx = blockIdx.x * 256 + threadIdx.x;
    g_h[idx] *= 0.25f;
}

// ------------------------------ GIN layer kernels ---------------------------
__global__ void k_initvn(const float* __restrict__ vemb) {
    int idx = blockIdx.x * 256 + threadIdx.x;
    g_vn[idx] = vemb[idx & 255];
}

__global__ void k_addvn() {
    int idx = blockIdx.x * 256 + threadIdx.x;
    int b = idx >> 16;
    int c = idx & 255;
    float v = g_h[idx] + g_vn[b*EMB + c];
    g_h[idx] = v;
    g_hin[idx] = v;
}

__global__ void k_agg(const float* __restrict__ eembL, const float* __restrict__ epsp) {
    int n = blockIdx.x, c = threadIdx.x;
    int start = g_ptr[n], deg = g_deg[n];
    float val = 0.f;
    for (int k = 0; k < deg; k++) {
        int s = g_csrc[start + k];
        int t = g_cea [start + k];
        float m = g_h[(size_t)s*EMB + c] + eembL[t*EMB + c];
        val += fmaxf(m, 0.f);
    }
    float eps = *epsp;
    float z = (1.f + eps) * g_h[(size_t)n*EMB + c] + val;
    splitw(z, g_zh, g_zl, (size_t)n*EMB + c);
}

// ------------------------------ batchnorm -----------------------------------
__global__ void k_zstat() {
    int i = blockIdx.x * 256 + threadIdx.x;
    if (i < 2*EMB) { g_sum[i] = 0.f; g_sq[i] = 0.f; }
}

__global__ void k_bnstats(const float* __restrict__ X, int C) {
    int r0 = blockIdx.x * 128;
    for (int c = threadIdx.x; c < C; c += 256) {
        float s = 0.f, q = 0.f;
        for (int r = 0; r < 128; r++) {
            float v = X[(size_t)(r0 + r)*C + c];
            s += v; q += v * v;
        }
        atomicAdd(&g_sum[c], s);
        atomicAdd(&g_sq[c], q);
    }
}

__global__ void k_bnfin(const float* __restrict__ g, const float* __restrict__ b, int C) {
    int c = blockIdx.x * 256 + threadIdx.x;
    if (c >= C) return;
    float mu  = g_sum[c] * (1.f / NTOT);
    float var = g_sq[c] * (1.f / NTOT) - mu * mu;
    float sc  = g[c] * rsqrtf(var + 1e-5f);
    g_scale[c] = sc;
    g_shift[c] = b[c] - mu * sc;
}

// BN1 apply + relu -> bf16 planes (feeds GEMM2)
__global__ void k_bnapplyS(const float* __restrict__ X) {
    int idx = blockIdx.x * 256 + threadIdx.x;
    int c = idx & (2*EMB - 1);
    float v = fmaxf(X[idx] * g_scale[c] + g_shift[c], 0.f);
    splitw(v, g_th, g_tl, idx);
}

// BN2 apply -> fp32 (p_h or final output)
__global__ void k_bnapply(const float* __restrict__ X, float* __restrict__ O, int act) {
    int idx = blockIdx.x * 256 + threadIdx.x;
    int c = idx & 255;
    float v = X[idx] * g_scale[c] + g_shift[c];
    if (act) v = fmaxf(v, 0.f);
    O[idx] = v;
}

__global__ void k_vt() {
    int b = blockIdx.x, c = threadIdx.x;
    const float* base = g_hin + (size_t)b*NPG*EMB + c;
    float s = 0.f;
    for (int r = 0; r < NPG; r++) s += base[(size_t)r*EMB];
    splitw(s + g_vn[b*EMB + c], g_vth, g_vtl, b*EMB + c);
}

// ------------------------------ host orchestration --------------------------
extern "C" void kernel_launch(void* const* d_in, const int* in_sizes, int n_in,
                              void* d_out, int out_size) {
    const int ab = n_in - 19;
    const int*   atom_idx = (const int*)  d_in[0];
    const int*   lei      = (const int*)  d_in[1];
    const int*   eai      = (const int*)  d_in[2];
    const float* atom_emb = (const float*)d_in[ab + 0];
    const float* bemb_h   = (const float*)d_in[ab + 1];
    const float* elin_w   = (const float*)d_in[ab + 2];
    const float* elin_b   = (const float*)d_in[ab + 3];
    const float* bemb_l   = (const float*)d_in[ab + 4];
    const float* gin_eps  = (const float*)d_in[ab + 5];
    const float* mlp_w1   = (const float*)d_in[ab + 6];
    const float* mlp_b1   = (const float*)d_in[ab + 7];
    const float* bn_g     = (const float*)d_in[ab + 8];
    const float* bn_b     = (const float*)d_in[ab + 9];
    const float* mlp_w2   = (const float*)d_in[ab + 10];
    const float* mlp_b2   = (const float*)d_in[ab + 11];
    const float* obn_g    = (const float*)d_in[ab + 12];
    const float* obn_b    = (const float*)d_in[ab + 13];
    const float* vn_emb   = (const float*)d_in[ab + 14];
    const float* vn_w1    = (const float*)d_in[ab + 15];
    const float* vn_b1    = (const float*)d_in[ab + 16];
    const float* vn_w2    = (const float*)d_in[ab + 17];
    const float* vn_b2    = (const float*)d_in[ab + 18];
    float* out = (float*)d_out;

    static int smem_set = 0;
    if (!smem_set) {
        cudaFuncSetAttribute(k_mma, cudaFuncAttributeMaxDynamicSharedMemorySize, SMEM_BYTES);
        smem_set = 1;
    }

    float *p_t, *p_h2, *p_h, *p_vn;
    cudaGetSymbolAddress((void**)&p_t,  g_t);
    cudaGetSymbolAddress((void**)&p_h2, g_h2);
    cudaGetSymbolAddress((void**)&p_h,  g_h);
    cudaGetSymbolAddress((void**)&p_vn, g_vn);
    bf16 *pAh, *pAl, *px1h, *px1l, *px2h, *px2l, *pzh, *pzl, *pth, *ptl;
    bf16 *pvth, *pvtl, *pvhh, *pvhl, *pw1h, *pw1l, *pw2h, *pw2l, *pu1h, *pu1l, *pu2h, *pu2l;
    cudaGetSymbolAddress((void**)&pAh,  g_Ahp);
    cudaGetSymbolAddress((void**)&pAl,  g_Alp);
    cudaGetSymbolAddress((void**)&px1h, g_x1h);
    cudaGetSymbolAddress((void**)&px1l, g_x1l);
    cudaGetSymbolAddress((void**)&px2h, g_x2h);
    cudaGetSymbolAddress((void**)&px2l, g_x2l);
    cudaGetSymbolAddress((void**)&pzh,  g_zh);
    cudaGetSymbolAddress((void**)&pzl,  g_zl);
    cudaGetSymbolAddress((void**)&pth,  g_th);
    cudaGetSymbolAddress((void**)&ptl,  g_tl);
    cudaGetSymbolAddress((void**)&pvth, g_vth);
    cudaGetSymbolAddress((void**)&pvtl, g_vtl);
    cudaGetSymbolAddress((void**)&pvhh, g_vhh);
    cudaGetSymbolAddress((void**)&pvhl, g_vhl);
    cudaGetSymbolAddress((void**)&pw1h, g_w1h);
    cudaGetSymbolAddress((void**)&pw1l, g_w1l);
    cudaGetSymbolAddress((void**)&pw2h, g_w2h);
    cudaGetSymbolAddress((void**)&pw2l, g_w2l);
    cudaGetSymbolAddress((void**)&pu1h, g_u1h);
    cudaGetSymbolAddress((void**)&pu1l, g_u1l);
    cudaGetSymbolAddress((void**)&pu2h, g_u2h);
    cudaGetSymbolAddress((void**)&pu2l, g_u2l);

    const int NE = NTOT*EMB/256;
    const int W  = EMB*2*EMB;     // 131072 per layer

    // ---- setup ----
    k_zero<<<(int)(((size_t)BG*NPG*NPG + 255)/256), 256>>>();
    k_ewt<<<1, 512>>>(bemb_h, elin_w, elin_b);
    k_scatter<<<ETOT/256, 256>>>(lei, eai);
    k_adjfin<<<BG, 256>>>();
    k_scan<<<BG, 256>>>();
    k_csrfill<<<ETOT/256, 256>>>(lei, eai);
    k_gather<<<NE, 256>>>(atom_idx, atom_emb);
    k_split<<<NL*W/256, 256>>>(mlp_w1, pw1h, pw1l, NL*W);
    k_split<<<NL*W/256, 256>>>(mlp_w2, pw2h, pw2l, NL*W);
    k_split<<<(NL-1)*W/256, 256>>>(vn_w1, pu1h, pu1l, (NL-1)*W);
    k_split<<<(NL-1)*W/256, 256>>>(vn_w2, pu2h, pu2l, (NL-1)*W);

    // ---- propagation: h = 0.25*(f + Af + A^2 f + A^3 f) ----
    dim3 pg(EMB/BN, NPG/BM, BG);   // (4, 2, 128)
    long sAdj = (long)NPG*NPG, sX = (long)NPG*EMB;
    k_mma<<<pg, 256, SMEM_BYTES>>>(pAh, pAl, px1h, px1l, nullptr,
                                   nullptr, px2h, px2l, p_h, 0, NPG, EMB, NPG, sAdj, sX, sX);
    k_mma<<<pg, 256, SMEM_BYTES>>>(pAh, pAl, px2h, px2l, nullptr,
                                   nullptr, px1h, px1l, p_h, 0, NPG, EMB, NPG, sAdj, sX, sX);
    k_mma<<<pg, 256, SMEM_BYTES>>>(pAh, pAl, px1h, px1l, nullptr,
                                   nullptr, px2h, px2l, p_h, 0, NPG, EMB, NPG, sAdj, sX, sX);
    k_scale<<<NE, 256>>>();

    k_initvn<<<BG*EMB/256, 256>>>(vn_emb);

    // ---- GIN + virtual-node stack ----
    for (int l = 0; l < NL; l++) {
        k_addvn<<<NE, 256>>>();
        k_agg<<<NTOT, 256>>>(bemb_l + (size_t)l*16*EMB, gin_eps + l);

        // GEMM1: t = z @ w1 + b1  [N, 512] fp32
        k_mma<<<dim3(2*EMB/BN, NTOT/BM, 1), 256, SMEM_BYTES>>>(
            pzh, pzl, pw1h + (size_t)l*W, pw1l + (size_t)l*W, mlp_b1 + (size_t)l*2*EMB,
            p_t, nullptr, nullptr, nullptr, 0, NTOT, 2*EMB, EMB, 0, 0, 0);
        // BN1 stats + apply(relu) -> t planes
        k_zstat<<<2, 256>>>();
        k_bnstats<<<NTOT/128, 256>>>(p_t, 2*EMB);
        k_bnfin<<<2, 256>>>(bn_g + (size_t)l*2*EMB, bn_b + (size_t)l*2*EMB, 2*EMB);
        k_bnapplyS<<<NTOT*2*EMB/256, 256>>>(p_t);

        // GEMM2: h2 = t' @ w2 + b2  [N, 256] fp32
        k_mma<<<dim3(EMB/BN, NTOT/BM, 1), 256, SMEM_BYTES>>>(
            pth, ptl, pw2h + (size_t)l*W, pw2l + (size_t)l*W, mlp_b2 + (size_t)l*EMB,
            p_h2, nullptr, nullptr, nullptr, 0, NTOT, EMB, 2*EMB, 0, 0, 0);
        // BN2 stats + apply
        k_zstat<<<2, 256>>>();
        k_bnstats<<<NTOT/128, 256>>>(p_h2, EMB);
        k_bnfin<<<1, 256>>>(obn_g + (size_t)l*EMB, obn_b + (size_t)l*EMB, EMB);
        if (l < NL - 1)
            k_bnapply<<<NE, 256>>>(p_h2, p_h, 1);
        else
            k_bnapply<<<NE, 256>>>(p_h2, out, 0);

        // virtual node update
        if (l < NL - 1) {
            k_vt<<<BG, 256>>>();
            k_mma<<<dim3(2*EMB/BN, 1, 1), 256, SMEM_BYTES>>>(
                pvth, pvtl, pu1h + (size_t)l*W, pu1l + (size_t)l*W, vn_b1 + (size_t)l*2*EMB,
                nullptr, pvhh, pvhl, nullptr, 1, BG*0 + 128, 2*EMB, EMB, 0, 0, 0);
            k_mma<<<dim3(EMB/BN, 1, 1), 256, SMEM_BYTES>>>(
                pvhh, pvhl, pu2h + (size_t)l*W, pu2l + (size_t)l*W, vn_b2 + (size_t)l*EMB,
                p_vn, nullptr, nullptr, nullptr, 1, 128, EMB, 2*EMB, 0, 0, 0);
        }
    }

    (void)in_sizes; (void)out_size;
}

// round 8
// speedup vs baseline: 1.5662x; 1.0867x over previous
#include <cuda_runtime.h>
#include <cuda_bf16.h>
#include <math.h>

#define BG   128
#define NPG  256
#define EPG  2048
#define EMB  256
#define NL   5
#define NTOT (BG*NPG)     // 32768 nodes
#define ETOT (BG*EPG)     // 262144 edges

typedef unsigned long long ull;
typedef __nv_bfloat16 bf16;

// ------------------------------ scratch (device globals; no allocs) ---------
__device__ ull   g_pack[(size_t)BG*NPG*NPG];
__device__ float g_cs [BG*NPG];      // rsqrt(col sums)
__device__ float g_rs [BG*NPG];      // rsqrt(row sums)
__device__ float g_h  [NTOT*EMB];
__device__ float g_hin[NTOT*EMB];
__device__ float g_t  [NTOT*2*EMB];
__device__ float g_h2 [NTOT*EMB];
__device__ float g_vn [BG*EMB];
__device__ float g_ewt[16];
__device__ int   g_deg[NTOT];
__device__ int   g_ptr[NTOT];
__device__ int   g_cur[NTOT];
__device__ int   g_csrc[ETOT];
__device__ int   g_cea [ETOT];
__device__ float g_sum[2*EMB];       // zero-init by module load; re-zeroed by k_bnfin
__device__ float g_sq [2*EMB];
__device__ float g_scale[2*EMB];
__device__ float g_shift[2*EMB];

// bf16 hi/lo planes (GEMM operands)
__device__ __align__(16) bf16 g_Ahp[(size_t)BG*NPG*NPG], g_Alp[(size_t)BG*NPG*NPG];
__device__ __align__(16) bf16 g_x1h[NTOT*EMB], g_x1l[NTOT*EMB];
__device__ __align__(16) bf16 g_x2h[NTOT*EMB], g_x2l[NTOT*EMB];
__device__ __align__(16) bf16 g_zh [NTOT*EMB], g_zl [NTOT*EMB];
__device__ __align__(16) bf16 g_th [NTOT*2*EMB], g_tl [NTOT*2*EMB];
__device__ __align__(16) bf16 g_vth[BG*EMB],   g_vtl[BG*EMB];
__device__ __align__(16) bf16 g_vhh[BG*2*EMB], g_vhl[BG*2*EMB];
__device__ __align__(16) bf16 g_w1h[NL*EMB*2*EMB],  g_w1l[NL*EMB*2*EMB];
__device__ __align__(16) bf16 g_w2h[NL*2*EMB*EMB],  g_w2l[NL*2*EMB*EMB];
__device__ __align__(16) bf16 g_u1h[(NL-1)*EMB*2*EMB], g_u1l[(NL-1)*EMB*2*EMB];
__device__ __align__(16) bf16 g_u2h[(NL-1)*2*EMB*EMB], g_u2l[(NL-1)*2*EMB*EMB];

__device__ __forceinline__ void splitw(float v, bf16* __restrict__ h,
                                       bf16* __restrict__ l, size_t i) {
    bf16 hv = __float2bfloat16(v);
    h[i] = hv;
    l[i] = __float2bfloat16(v - __bfloat162float(hv));
}

// ------------------------------ setup kernels -------------------------------
__global__ void k_zero() {
    size_t i = (size_t)blockIdx.x * 256 + threadIdx.x;
    if (i < (size_t)BG*NPG*NPG) g_pack[i] = 0ull;
    if (i < NTOT) g_deg[i] = 0;
}

__global__ void k_ewt(const float* __restrict__ bh, const float* __restrict__ w,
                      const float* __restrict__ b) {
    int warp = threadIdx.x >> 5, lane = threadIdx.x & 31;
    if (warp < 16) {
        float v = bh[warp*64 + lane] * w[lane] + bh[warp*64 + 32 + lane] * w[32 + lane];
        #pragma unroll
        for (int o = 16; o; o >>= 1) v += __shfl_down_sync(0xffffffffu, v, o);
        if (lane == 0) g_ewt[warp] = 1.f / (1.f + expf(-(v + b[0])));
    }
}

__global__ void k_scatter(const int* __restrict__ lei, const int* __restrict__ eai) {
    int idx = blockIdx.x * 256 + threadIdx.x;
    if (idx >= ETOT) return;
    int b = idx / EPG, k = idx - b * EPG;
    int s = lei[(size_t)b*2*EPG + k];
    int d = lei[(size_t)b*2*EPG + EPG + k];
    int t = eai[idx];
    float w = g_ewt[t];
    ull key = ((ull)(k + 1) << 32) | (ull)__float_as_uint(w);
    atomicMax(&g_pack[(size_t)b*NPG*NPG + (size_t)s*NPG + d], key);
    atomicAdd(&g_deg[b*NPG + d], 1);
}

// per-graph row/col sums of (adj + I), parallel across 8 warps
__global__ void k_adjprep() {
    int g = blockIdx.x;
    int tid = threadIdx.x, lane = tid & 31, warp = tid >> 5;
    __shared__ float s_cs[NPG], s_rs[NPG];
    for (int i = tid; i < NPG; i += 256) s_cs[i] = 0.f;
    __syncthreads();
    const ull* P = g_pack + (size_t)g*NPG*NPG;
    float csl[8] = {};
    for (int rb = 0; rb < NPG; rb += 8) {
        int r = rb + warp;
        float rsum = 0.f;
        #pragma unroll
        for (int k = 0; k < 8; k++) {
            int c = lane + k*32;
            ull p = P[(size_t)r*NPG + c];
            float v = p ? __uint_as_float((unsigned)(p & 0xffffffffu)) : 0.f;
            if (r == c) v += 1.f;
            rsum += v;
            csl[k] += v;
        }
        #pragma unroll
        for (int o = 16; o; o >>= 1) rsum += __shfl_down_sync(0xffffffffu, rsum, o);
        if (lane == 0) s_rs[r] = rsqrtf(rsum);
    }
    #pragma unroll
    for (int k = 0; k < 8; k++) atomicAdd(&s_cs[lane + k*32], csl[k]);
    __syncthreads();
    for (int i = tid; i < NPG; i += 256) {
        g_cs[g*NPG + i] = rsqrtf(s_cs[i]);
        g_rs[g*NPG + i] = s_rs[i];
    }
}

// fully parallel normalize + split to bf16 planes (no fp32 A buffer)
__global__ void k_adjnorm() {
    size_t idx = (size_t)blockIdx.x * 256 + threadIdx.x;
    int g = (int)(idx >> 16);
    int r = (int)((idx >> 8) & 255);
    int c = (int)(idx & 255);
    ull p = g_pack[idx];
    float v = p ? __uint_as_float((unsigned)(p & 0xffffffffu)) : 0.f;
    if (r == c) v += 1.f;
    v *= g_cs[g*NPG + r] * g_rs[g*NPG + c];
    splitw(v, g_Ahp, g_Alp, idx);
}

__global__ void k_scan() {
    int g = blockIdx.x, tid = threadIdx.x;
    __shared__ int s[NPG];
    int d = g_deg[g*NPG + tid];
    s[tid] = d;
    __syncthreads();
    for (int off = 1; off < NPG; off <<= 1) {
        int v = (tid >= off) ? s[tid - off] : 0;
        __syncthreads();
        s[tid] += v;
        __syncthreads();
    }
    int excl = s[tid] - d;
    g_ptr[g*NPG + tid] = g*EPG + excl;
    g_cur[g*NPG + tid] = g*EPG + excl;
}

__global__ void k_csrfill(const int* __restrict__ lei, const int* __restrict__ eai) {
    int idx = blockIdx.x * 256 + threadIdx.x;
    if (idx >= ETOT) return;
    int b = idx / EPG, k = idx - b * EPG;
    int s = lei[(size_t)b*2*EPG + k];
    int d = lei[(size_t)b*2*EPG + EPG + k];
    int pos = atomicAdd(&g_cur[b*NPG + d], 1);
    g_csrc[pos] = b*NPG + s;
    g_cea [pos] = eai[idx];
}

__global__ void k_gather(const int* __restrict__ aidx, const float* __restrict__ aemb) {
    int idx = blockIdx.x * 256 + threadIdx.x;
    int n = idx >> 8, c = idx & 255;
    float v = aemb[aidx[n]*EMB + c];
    g_h[idx] = v;
    splitw(v, g_x1h, g_x1l, idx);
}

__global__ void k_split(const float* __restrict__ w, bf16* __restrict__ h,
                        bf16* __restrict__ l, int n) {
    int i = blockIdx.x * 256 + threadIdx.x;
    if (i < n) splitw(w[i], h, l, i);
}

// ------------------------------ pipelined bf16x3 tensor GEMM ----------------
#define BM 128
#define BN 64
#define APAD 40
#define BPAD 72
#define ASEG (128*APAD)
#define BSEG (32*BPAD)
#define BBASE (6*ASEG)
#define SMEM_BYTES ((6*ASEG + 6*BSEG)*2)   // 89088

__device__ __forceinline__ void cpa16(unsigned s, const void* g) {
    asm volatile("cp.async.cg.shared.global [%0], [%1], 16;" :: "r"(s), "l"(g));
}
#define LDSM4(r0,r1,r2,r3,a)                                                   \
    asm volatile("ldmatrix.sync.aligned.m8n8.x4.shared.b16 {%0,%1,%2,%3}, [%4];" \
        : "=r"(r0),"=r"(r1),"=r"(r2),"=r"(r3) : "r"(a))
#define LDSM4T(r0,r1,r2,r3,a)                                                  \
    asm volatile("ldmatrix.sync.aligned.m8n8.x4.trans.shared.b16 {%0,%1,%2,%3}, [%4];" \
        : "=r"(r0),"=r"(r1),"=r"(r2),"=r"(r3) : "r"(a))
#define MMA_BF16(c, a, b)                                                     \
    asm volatile(                                                             \
        "mma.sync.aligned.m16n8k16.row.col.f32.bf16.bf16.f32 "                \
        "{%0,%1,%2,%3}, {%4,%5,%6,%7}, {%8,%9}, {%0,%1,%2,%3};\n"             \
        : "+f"((c)[0]), "+f"((c)[1]), "+f"((c)[2]), "+f"((c)[3])              \
        : "r"((a)[0]), "r"((a)[1]), "r"((a)[2]), "r"((a)[3]),                 \
          "r"((b)[0]), "r"((b)[1]))

__global__ void __launch_bounds__(256, 2)
k_mma(const bf16* __restrict__ Ah, const bf16* __restrict__ Al,
      const bf16* __restrict__ Bh, const bf16* __restrict__ Bl,
      const float* __restrict__ bias,
      float* __restrict__ Cf, bf16* __restrict__ Chi, bf16* __restrict__ Clo,
      float* __restrict__ Y, int relu,
      int M, int N, int K, long sA, long sB, long sC) {
    extern __shared__ bf16 smbuf[];
    Ah += (size_t)blockIdx.z * sA;  Al += (size_t)blockIdx.z * sA;
    Bh += (size_t)blockIdx.z * sB;  Bl += (size_t)blockIdx.z * sB;
    if (Cf)  Cf  += (size_t)blockIdx.z * sC;
    if (Chi) { Chi += (size_t)blockIdx.z * sC; Clo += (size_t)blockIdx.z * sC; }
    if (Y)   Y   += (size_t)blockIdx.z * sC;

    unsigned sb = (unsigned)__cvta_generic_to_shared(smbuf);
    int tid = threadIdx.x, lane = tid & 31, warp = tid >> 5;
    int wm = warp >> 1, wn = warp & 1;
    int bm = blockIdx.y * BM, bn = blockIdx.x * BN;

    int ar = tid >> 2, ac = (tid & 3) * 8;
    int br = tid >> 3, bc = (tid & 7) * 8;
    int lr = lane & 15, lc = (lane >> 4) * 8;

    float acc[2][4][4];
    #pragma unroll
    for (int i = 0; i < 2; i++)
        #pragma unroll
        for (int j = 0; j < 4; j++)
            #pragma unroll
            for (int r = 0; r < 4; r++) acc[i][j][r] = 0.f;

    int niter = K / 32;

#define ISSUE(buf, kk) {                                                         \
    unsigned a0 = sb + (unsigned)(((buf)*2+0)*ASEG)*2;                            \
    unsigned a1 = sb + (unsigned)(((buf)*2+1)*ASEG)*2;                            \
    unsigned b0 = sb + (unsigned)((BBASE + ((buf)*2+0)*BSEG))*2;                  \
    unsigned b1 = sb + (unsigned)((BBASE + ((buf)*2+1)*BSEG))*2;                  \
    cpa16(a0 + (ar*APAD + ac)*2,      Ah + (size_t)(bm + ar)*K + (kk) + ac);      \
    cpa16(a0 + ((ar+64)*APAD + ac)*2, Ah + (size_t)(bm + ar + 64)*K + (kk) + ac); \
    cpa16(a1 + (ar*APAD + ac)*2,      Al + (size_t)(bm + ar)*K + (kk) + ac);      \
    cpa16(a1 + ((ar+64)*APAD + ac)*2, Al + (size_t)(bm + ar + 64)*K + (kk) + ac); \
    cpa16(b0 + (br*BPAD + bc)*2,      Bh + (size_t)((kk) + br)*N + bn + bc);      \
    cpa16(b1 + (br*BPAD + bc)*2,      Bl + (size_t)((kk) + br)*N + bn + bc);      \
}

    ISSUE(0, 0);
    asm volatile("cp.async.commit_group;");
    ISSUE(1, 32);
    asm volatile("cp.async.commit_group;");

    int cbuf = 0, ibuf = 2;
    for (int it = 0; it < niter; it++) {
        asm volatile("cp.async.wait_group 1;");
        __syncthreads();
        if (it + 2 < niter) { int kk = (it + 2) * 32; ISSUE(ibuf, kk); }
        asm volatile("cp.async.commit_group;");

        unsigned aH = sb + (unsigned)((cbuf*2+0)*ASEG)*2;
        unsigned aL = sb + (unsigned)((cbuf*2+1)*ASEG)*2;
        unsigned bH = sb + (unsigned)((BBASE + (cbuf*2+0)*BSEG))*2;
        unsigned bL = sb + (unsigned)((BBASE + (cbuf*2+1)*BSEG))*2;

        #pragma unroll
        for (int ks = 0; ks < 2; ks++) {
            unsigned ah[2][4], al[2][4], bh[4][2], bl[4][2];
            #pragma unroll
            for (int mf = 0; mf < 2; mf++) {
                unsigned off = (unsigned)(((wm*32 + mf*16 + lr)*APAD + ks*16 + lc)*2);
                LDSM4(ah[mf][0], ah[mf][1], ah[mf][2], ah[mf][3], aH + off);
                LDSM4(al[mf][0], al[mf][1], al[mf][2], al[mf][3], aL + off);
            }
            #pragma unroll
            for (int p = 0; p < 2; p++) {
                unsigned off = (unsigned)(((ks*16 + lr)*BPAD + wn*32 + p*16 + lc)*2);
                unsigned r0, r1, r2, r3;
                LDSM4T(r0, r1, r2, r3, bH + off);
                bh[2*p][0] = r0; bh[2*p][1] = r1; bh[2*p+1][0] = r2; bh[2*p+1][1] = r3;
                LDSM4T(r0, r1, r2, r3, bL + off);
                bl[2*p][0] = r0; bl[2*p][1] = r1; bl[2*p+1][0] = r2; bl[2*p+1][1] = r3;
            }
            #pragma unroll
            for (int mf = 0; mf < 2; mf++)
                #pragma unroll
                for (int nf = 0; nf < 4; nf++) {
                    float* c = acc[mf][nf];
                    MMA_BF16(c, ah[mf], bl[nf]);
                    MMA_BF16(c, al[mf], bh[nf]);
                    MMA_BF16(c, ah[mf], bh[nf]);
                }
        }
        cbuf = (cbuf == 2) ? 0 : cbuf + 1;
        ibuf = (ibuf == 2) ? 0 : ibuf + 1;
    }

    // ---- epilogue ----
    int gid = lane >> 2, tig = lane & 3;
    #pragma unroll
    for (int mf = 0; mf < 2; mf++) {
        #pragma unroll
        for (int nf = 0; nf < 4; nf++) {
            int r0 = bm + wm*32 + mf*16 + gid;
            int c0 = bn + wn*32 + nf*8 + 2*tig;
            float b0 = 0.f, b1 = 0.f;
            if (bias) { b0 = bias[c0]; b1 = bias[c0+1]; }
            float* c = acc[mf][nf];
            #pragma unroll
            for (int half = 0; half < 2; half++) {
                int r = r0 + half*8;
                float v0 = c[half*2+0] + b0, v1 = c[half*2+1] + b1;
                if (relu) { v0 = fmaxf(v0, 0.f); v1 = fmaxf(v1, 0.f); }
                if (Cf)
                    *reinterpret_cast<float2*>(Cf + (size_t)r*N + c0) = make_float2(v0, v1);
                if (Chi) {
                    bf16 h0 = __float2bfloat16(v0), h1 = __float2bfloat16(v1);
                    *reinterpret_cast<__nv_bfloat162*>(Chi + (size_t)r*N + c0) =
                        __halves2bfloat162(h0, h1);
                    bf16 l0 = __float2bfloat16(v0 - __bfloat162float(h0));
                    bf16 l1 = __float2bfloat16(v1 - __bfloat162float(h1));
                    *reinterpret_cast<__nv_bfloat162*>(Clo + (size_t)r*N + c0) =
                        __halves2bfloat162(l0, l1);
                }
                if (Y) {
                    float2* y = reinterpret_cast<float2*>(Y + (size_t)r*N + c0);
                    float2 yo = *y;
                    yo.x += v0; yo.y += v1;
                    *y = yo;
                }
            }
        }
    }
#undef ISSUE
}

// ------------------------------ fused GIN aggregate --------------------------
// hin = h*hscale + vn; z = (1+eps)*hin + sum_edges relu(h_src*hscale + vn + eemb)
__global__ void k_agg(const float* __restrict__ eembL, const float* __restrict__ epsp,
                      const float* __restrict__ vnp, int vnstride, float hscale) {
    int n = blockIdx.x, c = threadIdx.x;
    int b = n >> 8;
    float vnv = vnp[b*vnstride + c];
    int start = g_ptr[n], deg = g_deg[n];
    float own = g_h[(size_t)n*EMB + c] * hscale + vnv;
    g_hin[(size_t)n*EMB + c] = own;
    float val = 0.f;
    for (int k = 0; k < deg; k++) {
        int s = g_csrc[start + k];
        int t = g_cea [start + k];
        float m = g_h[(size_t)s*EMB + c] * hscale + vnv + eembL[t*EMB + c];
        val += fmaxf(m, 0.f);
    }
    float z = (1.f + *epsp) * own + val;
    splitw(z, g_zh, g_zl, (size_t)n*EMB + c);
}

// ------------------------------ batchnorm -----------------------------------
__global__ void k_bnstats(const float* __restrict__ X, int C) {
    int r0 = blockIdx.x * 128;
    for (int c = threadIdx.x; c < C; c += 256) {
        float s = 0.f, q = 0.f;
        for (int r = 0; r < 128; r++) {
            float v = X[(size_t)(r0 + r)*C + c];
            s += v; q += v * v;
        }
        atomicAdd(&g_sum[c], s);
        atomicAdd(&g_sq[c], q);
    }
}

// computes scale/shift AND re-zeroes the stats accumulators for the next use
__global__ void k_bnfin(const float* __restrict__ g, const float* __restrict__ b, int C) {
    int c = blockIdx.x * 256 + threadIdx.x;
    if (c >= C) return;
    float mu  = g_sum[c] * (1.f / NTOT);
    float var = g_sq[c] * (1.f / NTOT) - mu * mu;
    float sc  = g[c] * rsqrtf(var + 1e-5f);
    g_scale[c] = sc;
    g_shift[c] = b[c] - mu * sc;
    g_sum[c] = 0.f;
    g_sq[c]  = 0.f;
}

// BN1 apply + relu -> bf16 planes (feeds GEMM2)
__global__ void k_bnapplyS(const float* __restrict__ X) {
    int idx = blockIdx.x * 256 + threadIdx.x;
    int c = idx & (2*EMB - 1);
    float v = fmaxf(X[idx] * g_scale[c] + g_shift[c], 0.f);
    splitw(v, g_th, g_tl, idx);
}

// BN2 apply -> fp32 (h for next layer, or final output)
__global__ void k_bnapply(const float* __restrict__ X, float* __restrict__ O, int act) {
    int idx = blockIdx.x * 256 + threadIdx.x;
    int c = idx & 255;
    float v = X[idx] * g_scale[c] + g_shift[c];
    if (act) v = fmaxf(v, 0.f);
    O[idx] = v;
}

// vt[b] = sum_nodes hin + vn[b]
__global__ void k_vt(const float* __restrict__ vnp, int vnstride) {
    int b = blockIdx.x, c = threadIdx.x;
    const float* base = g_hin + (size_t)b*NPG*EMB + c;
    float s = 0.f;
    #pragma unroll 4
    for (int r = 0; r < NPG; r++) s += base[(size_t)r*EMB];
    splitw(s + vnp[b*vnstride + c], g_vth, g_vtl, b*EMB + c);
}

// ------------------------------ host orchestration --------------------------
extern "C" void kernel_launch(void* const* d_in, const int* in_sizes, int n_in,
                              void* d_out, int out_size) {
    const int ab = n_in - 19;
    const int*   atom_idx = (const int*)  d_in[0];
    const int*   lei      = (const int*)  d_in[1];
    const int*   eai      = (const int*)  d_in[2];
    const float* atom_emb = (const float*)d_in[ab + 0];
    const float* bemb_h   = (const float*)d_in[ab + 1];
    const float* elin_w   = (const float*)d_in[ab + 2];
    const float* elin_b   = (const float*)d_in[ab + 3];
    const float* bemb_l   = (const float*)d_in[ab + 4];
    const float* gin_eps  = (const float*)d_in[ab + 5];
    const float* mlp_w1   = (const float*)d_in[ab + 6];
    const float* mlp_b1   = (const float*)d_in[ab + 7];
    const float* bn_g     = (const float*)d_in[ab + 8];
    const float* bn_b     = (const float*)d_in[ab + 9];
    const float* mlp_w2   = (const float*)d_in[ab + 10];
    const float* mlp_b2   = (const float*)d_in[ab + 11];
    const float* obn_g    = (const float*)d_in[ab + 12];
    const float* obn_b    = (const float*)d_in[ab + 13];
    const float* vn_emb   = (const float*)d_in[ab + 14];
    const float* vn_w1    = (const float*)d_in[ab + 15];
    const float* vn_b1    = (const float*)d_in[ab + 16];
    const float* vn_w2    = (const float*)d_in[ab + 17];
    const float* vn_b2    = (const float*)d_in[ab + 18];
    float* out = (float*)d_out;

    static int smem_set = 0;
    if (!smem_set) {
        cudaFuncSetAttribute(k_mma, cudaFuncAttributeMaxDynamicSharedMemorySize, SMEM_BYTES);
        smem_set = 1;
    }

    float *p_t, *p_h2, *p_h, *p_vn;
    cudaGetSymbolAddress((void**)&p_t,  g_t);
    cudaGetSymbolAddress((void**)&p_h2, g_h2);
    cudaGetSymbolAddress((void**)&p_h,  g_h);
    cudaGetSymbolAddress((void**)&p_vn, g_vn);
    bf16 *pAh, *pAl, *px1h, *px1l, *px2h, *px2l, *pzh, *pzl, *pth, *ptl;
    bf16 *pvth, *pvtl, *pvhh, *pvhl, *pw1h, *pw1l, *pw2h, *pw2l, *pu1h, *pu1l, *pu2h, *pu2l;
    cudaGetSymbolAddress((void**)&pAh,  g_Ahp);
    cudaGetSymbolAddress((void**)&pAl,  g_Alp);
    cudaGetSymbolAddress((void**)&px1h, g_x1h);
    cudaGetSymbolAddress((void**)&px1l, g_x1l);
    cudaGetSymbolAddress((void**)&px2h, g_x2h);
    cudaGetSymbolAddress((void**)&px2l, g_x2l);
    cudaGetSymbolAddress((void**)&pzh,  g_zh);
    cudaGetSymbolAddress((void**)&pzl,  g_zl);
    cudaGetSymbolAddress((void**)&pth,  g_th);
    cudaGetSymbolAddress((void**)&ptl,  g_tl);
    cudaGetSymbolAddress((void**)&pvth, g_vth);
    cudaGetSymbolAddress((void**)&pvtl, g_vtl);
    cudaGetSymbolAddress((void**)&pvhh, g_vhh);
    cudaGetSymbolAddress((void**)&pvhl, g_vhl);
    cudaGetSymbolAddress((void**)&pw1h, g_w1h);
    cudaGetSymbolAddress((void**)&pw1l, g_w1l);
    cudaGetSymbolAddress((void**)&pw2h, g_w2h);
    cudaGetSymbolAddress((void**)&pw2l, g_w2l);
    cudaGetSymbolAddress((void**)&pu1h, g_u1h);
    cudaGetSymbolAddress((void**)&pu1l, g_u1l);
    cudaGetSymbolAddress((void**)&pu2h, g_u2h);
    cudaGetSymbolAddress((void**)&pu2l, g_u2l);

    const int NE = NTOT*EMB/256;
    const int W  = EMB*2*EMB;

    // ---- setup ----
    k_zero<<<(int)(((size_t)BG*NPG*NPG + 255)/256), 256>>>();
    k_ewt<<<1, 512>>>(bemb_h, elin_w, elin_b);
    k_scatter<<<ETOT/256, 256>>>(lei, eai);
    k_adjprep<<<BG, 256>>>();
    k_adjnorm<<<(int)((size_t)BG*NPG*NPG/256), 256>>>();
    k_scan<<<BG, 256>>>();
    k_csrfill<<<ETOT/256, 256>>>(lei, eai);
    k_gather<<<NE, 256>>>(atom_idx, atom_emb);
    k_split<<<NL*W/256, 256>>>(mlp_w1, pw1h, pw1l, NL*W);
    k_split<<<NL*W/256, 256>>>(mlp_w2, pw2h, pw2l, NL*W);
    k_split<<<(NL-1)*W/256, 256>>>(vn_w1, pu1h, pu1l, (NL-1)*W);
    k_split<<<(NL-1)*W/256, 256>>>(vn_w2, pu2h, pu2l, (NL-1)*W);

    // ---- propagation: g_h accumulates f + Af + A^2 f + A^3 f (scale folded into k_agg) ----
    dim3 pg(EMB/BN, NPG/BM, BG);
    long sAdj = (long)NPG*NPG, sX = (long)NPG*EMB;
    k_mma<<<pg, 256, SMEM_BYTES>>>(pAh, pAl, px1h, px1l, nullptr,
                                   nullptr, px2h, px2l, p_h, 0, NPG, EMB, NPG, sAdj, sX, sX);
    k_mma<<<pg, 256, SMEM_BYTES>>>(pAh, pAl, px2h, px2l, nullptr,
                                   nullptr, px1h, px1l, p_h, 0, NPG, EMB, NPG, sAdj, sX, sX);
    k_mma<<<pg, 256, SMEM_BYTES>>>(pAh, pAl, px1h, px1l, nullptr,
                                   nullptr, px2h, px2l, p_h, 0, NPG, EMB, NPG, sAdj, sX, sX);

    // ---- GIN + virtual-node stack ----
    const float* vnp = vn_emb;    // layer-0 vn (broadcast, stride 0)
    int vnstride = 0;

    for (int l = 0; l < NL; l++) {
        float hscale = (l == 0) ? 0.25f : 1.0f;   // /(order+1) folded in at layer 0
        k_agg<<<NTOT, 256>>>(bemb_l + (size_t)l*16*EMB, gin_eps + l, vnp, vnstride, hscale);

        // GEMM1: t = z @ w1 + b1  [N, 512] fp32
        k_mma<<<dim3(2*EMB/BN, NTOT/BM, 1), 256, SMEM_BYTES>>>(
            pzh, pzl, pw1h + (size_t)l*W, pw1l + (size_t)l*W, mlp_b1 + (size_t)l*2*EMB,
            p_t, nullptr, nullptr, nullptr, 0, NTOT, 2*EMB, EMB, 0, 0, 0);
        k_bnstats<<<NTOT/128, 256>>>(p_t, 2*EMB);
        k_bnfin<<<2, 256>>>(bn_g + (size_t)l*2*EMB, bn_b + (size_t)l*2*EMB, 2*EMB);
        k_bnapplyS<<<NTOT*2*EMB/256, 256>>>(p_t);

        // GEMM2: h2 = t' @ w2 + b2  [N, 256] fp32
        k_mma<<<dim3(EMB/BN, NTOT/BM, 1), 256, SMEM_BYTES>>>(
            pth, ptl, pw2h + (size_t)l*W, pw2l + (size_t)l*W, mlp_b2 + (size_t)l*EMB,
            p_h2, nullptr, nullptr, nullptr, 0, NTOT, EMB, 2*EMB, 0, 0, 0);
        k_bnstats<<<NTOT/128, 256>>>(p_h2, EMB);
        k_bnfin<<<1, 256>>>(obn_g + (size_t)l*EMB, obn_b + (size_t)l*EMB, EMB);
        if (l < NL - 1)
            k_bnapply<<<NE, 256>>>(p_h2, p_h, 1);
        else
            k_bnapply<<<NE, 256>>>(p_h2, out, 0);

        // virtual node update (uses hin, which already includes vn)
        if (l < NL - 1) {
            k_vt<<<BG, 256>>>(vnp, vnstride);
            k_mma<<<dim3(2*EMB/BN, 1, 1), 256, SMEM_BYTES>>>(
                pvth, pvtl, pu1h + (size_t)l*W, pu1l + (size_t)l*W, vn_b1 + (size_t)l*2*EMB,
                nullptr, pvhh, pvhl, nullptr, 1, 128, 2*EMB, EMB, 0, 0, 0);
            k_mma<<<dim3(EMB/BN, 1, 1), 256, SMEM_BYTES>>>(
                pvhh, pvhl, pu2h + (size_t)l*W, pu2l + (size_t)l*W, vn_b2 + (size_t)l*EMB,
                p_vn, nullptr, nullptr, nullptr, 1, 128, EMB, 2*EMB, 0, 0, 0);
        }

        vnp = p_vn; vnstride = EMB;
    }

    (void)in_sizes; (void)out_size;
}